// round 11
// baseline (speedup 1.0000x reference)
#include <cuda_runtime.h>
#include <cuda_bf16.h>
#include <math.h>
#include <stdint.h>

#define MTOT 8192      // 2*4096 rows
#define NDIM 512
#define SEQ  4096
#define DH   64
#define NT   (SEQ / 128)

// scratch (allocation-free rule -> device globals)
__device__ __nv_bfloat16 g_xb [MTOT * NDIM];
__device__ __nv_bfloat16 g_Wqb[NDIM * NDIM];
__device__ __nv_bfloat16 g_Wkb[NDIM * NDIM];
__device__ __nv_bfloat16 g_Wvb[NDIM * NDIM];
__device__ __nv_bfloat16 g_Wob[NDIM * NDIM];
__device__ __nv_bfloat16 g_Q  [MTOT * NDIM];   // pre-scaled x0.125
__device__ __nv_bfloat16 g_K  [MTOT * NDIM];
__device__ __nv_bfloat16 g_V  [MTOT * NDIM];
__device__ __nv_bfloat16 g_AO [MTOT * NDIM];

// ---------------------------------------------------------------------------
// helpers
// ---------------------------------------------------------------------------
static __device__ __forceinline__ uint32_t s2u(const void* p) {
    uint32_t a;
    asm("{ .reg .u64 t; cvta.to.shared.u64 t, %1; cvt.u32.u64 %0, t; }"
        : "=r"(a) : "l"(p));
    return a;
}
static __device__ __forceinline__ uint32_t packbf(float lo, float hi) {
    uint32_t r;
    asm("cvt.rn.bf16x2.f32 %0, %1, %2;" : "=r"(r) : "f"(hi), "f"(lo));
    return r;
}
static __device__ __forceinline__ void cpa16(uint32_t dst, const void* src) {
    asm volatile("cp.async.cg.shared.global [%0], [%1], 16;"
                 :: "r"(dst), "l"(src));
}
static __device__ __forceinline__ void cpa_commit() {
    asm volatile("cp.async.commit_group;" ::: "memory");
}
static __device__ __forceinline__ void cpa_wait0() {
    asm volatile("cp.async.wait_group 0;" ::: "memory");
}

#define MMA_BF16(c, a, b0, b1)                                              \
    asm volatile(                                                           \
        "mma.sync.aligned.m16n8k16.row.col.f32.bf16.bf16.f32 "              \
        "{%0,%1,%2,%3},{%4,%5,%6,%7},{%8,%9},{%0,%1,%2,%3};"                \
        : "+f"((c)[0]), "+f"((c)[1]), "+f"((c)[2]), "+f"((c)[3])            \
        : "r"((a)[0]), "r"((a)[1]), "r"((a)[2]), "r"((a)[3]),               \
          "r"(b0), "r"(b1))

#define LDSM_X4_T(r0, r1, r2, r3, addr)                                     \
    asm volatile(                                                           \
        "ldmatrix.sync.aligned.m8n8.x4.trans.shared.b16 {%0,%1,%2,%3}, [%4];"\
        : "=r"(r0), "=r"(r1), "=r"(r2), "=r"(r3) : "r"(addr))

// ---------------------------------------------------------------------------
// fp32 -> bf16 convert pre-pass (x; and the 4 weights in one launch)
// ---------------------------------------------------------------------------
__global__ void __launch_bounds__(256) cvt_kernel(const float* __restrict__ s,
                                                  __nv_bfloat16* __restrict__ d)
{
    const int i = (blockIdx.x * 256 + threadIdx.x) * 4;
    const float4 v = *(const float4*)(s + i);
    *(uint32_t*)(d + i)     = packbf(v.x, v.y);
    *(uint32_t*)(d + i + 2) = packbf(v.z, v.w);
}

__global__ void __launch_bounds__(256) cvtw_kernel(const float* __restrict__ wq,
                                                   const float* __restrict__ wk,
                                                   const float* __restrict__ wv,
                                                   const float* __restrict__ wo)
{
    const float* s;
    __nv_bfloat16* d;
    switch (blockIdx.z) {
        case 0:  s = wq; d = g_Wqb; break;
        case 1:  s = wk; d = g_Wkb; break;
        case 2:  s = wv; d = g_Wvb; break;
        default: s = wo; d = g_Wob; break;
    }
    const int i = (blockIdx.x * 256 + threadIdx.x) * 4;
    const float4 v = *(const float4*)(s + i);
    *(uint32_t*)(d + i)     = packbf(v.x, v.y);
    *(uint32_t*)(d + i + 2) = packbf(v.z, v.w);
}

// ---------------------------------------------------------------------------
// bf16 GEMM: C[m,n] = sum_k A[m,k] * B[n,k]
// CTA 128x128, kstep 32, 256 thr = 8 warps (4m x 2n), warp 32x64, m16n8k16.
// mode (RUNTIME, epilogue-only): 0 bf16 out (x scale); 2 fp32 out + residual.
// ---------------------------------------------------------------------------
static __device__ __forceinline__ void bgemm_body(
    const __nv_bfloat16* __restrict__ Ag, const __nv_bfloat16* __restrict__ Bg,
    __nv_bfloat16* __restrict__ Cb, float* __restrict__ Cf,
    const float* __restrict__ resid, int mode, float scale)
{
    __shared__ __nv_bfloat16 As[2][128 * 40];
    __shared__ __nv_bfloat16 Bs[2][128 * 40];

    const int tid = threadIdx.x;
    const int wid = tid >> 5, lane = tid & 31;
    const int g = lane >> 2, tc = lane & 3;
    const int wr = wid & 3, wn = wid >> 2;
    const int m0 = blockIdx.y * 128, n0 = blockIdx.x * 128;

    const uint32_t as0 = s2u(As[0]), as1 = s2u(As[1]);
    const uint32_t bs0 = s2u(Bs[0]), bs1 = s2u(Bs[1]);

    {
#pragma unroll
        for (int i = 0; i < 2; i++) {
            const int idx = tid + i * 256;
            const int r = idx >> 2, c = idx & 3;
            cpa16(as0 + r * 80 + c * 16, Ag + (size_t)(m0 + r) * NDIM + c * 8);
            cpa16(bs0 + r * 80 + c * 16, Bg + (size_t)(n0 + r) * NDIM + c * 8);
        }
        cpa_commit();
    }

    float cacc[2][8][4];
#pragma unroll
    for (int mi = 0; mi < 2; mi++)
#pragma unroll
        for (int ni = 0; ni < 8; ni++)
#pragma unroll
            for (int c = 0; c < 4; c++) cacc[mi][ni][c] = 0.f;

    for (int kb = 0; kb < 16; kb++) {
        cpa_wait0();
        __syncthreads();
        if (kb < 15) {
            const int k0 = (kb + 1) * 32;
            const uint32_t as = (kb & 1) ? as0 : as1;
            const uint32_t bs = (kb & 1) ? bs0 : bs1;
#pragma unroll
            for (int i = 0; i < 2; i++) {
                const int idx = tid + i * 256;
                const int r = idx >> 2, c = idx & 3;
                cpa16(as + r * 80 + c * 16, Ag + (size_t)(m0 + r) * NDIM + k0 + c * 8);
                cpa16(bs + r * 80 + c * 16, Bg + (size_t)(n0 + r) * NDIM + k0 + c * 8);
            }
            cpa_commit();
        }
        const uint32_t* Aw = (const uint32_t*)As[kb & 1];
        const uint32_t* Bw = (const uint32_t*)Bs[kb & 1];

#pragma unroll
        for (int h = 0; h < 2; h++) {
            const int kw = h * 8;
            uint32_t a[2][4];
#pragma unroll
            for (int mi = 0; mi < 2; mi++) {
                const int row = wr * 32 + mi * 16 + g;
                a[mi][0] = Aw[row * 20 + kw + tc];
                a[mi][1] = Aw[(row + 8) * 20 + kw + tc];
                a[mi][2] = Aw[row * 20 + kw + tc + 4];
                a[mi][3] = Aw[(row + 8) * 20 + kw + tc + 4];
            }
#pragma unroll
            for (int ni = 0; ni < 8; ni++) {
                const int br = wn * 64 + ni * 8 + g;
                const uint32_t b0 = Bw[br * 20 + kw + tc];
                const uint32_t b1 = Bw[br * 20 + kw + tc + 4];
                MMA_BF16(cacc[0][ni], a[0], b0, b1);
                MMA_BF16(cacc[1][ni], a[1], b0, b1);
            }
        }
    }

#pragma unroll
    for (int mi = 0; mi < 2; mi++) {
        const int row = m0 + wr * 32 + mi * 16 + g;
#pragma unroll
        for (int ni = 0; ni < 8; ni++) {
            const int col = n0 + wn * 64 + ni * 8 + tc * 2;
            if (mode == 2) {
                const float2 x0 = *(const float2*)(resid + (size_t)row * NDIM + col);
                const float2 x1 = *(const float2*)(resid + (size_t)(row + 8) * NDIM + col);
                *(float2*)(Cf + (size_t)row * NDIM + col) =
                    make_float2(cacc[mi][ni][0] + x0.x, cacc[mi][ni][1] + x0.y);
                *(float2*)(Cf + (size_t)(row + 8) * NDIM + col) =
                    make_float2(cacc[mi][ni][2] + x1.x, cacc[mi][ni][3] + x1.y);
            } else {
                *(uint32_t*)(Cb + (size_t)row * NDIM + col) =
                    packbf(cacc[mi][ni][0] * scale, cacc[mi][ni][1] * scale);
                *(uint32_t*)(Cb + (size_t)(row + 8) * NDIM + col) =
                    packbf(cacc[mi][ni][2] * scale, cacc[mi][ni][3] * scale);
            }
        }
    }
}

__global__ void __launch_bounds__(256) qkv_bgemm_kernel()
{
    const int z = blockIdx.z;
    const __nv_bfloat16* B = (z == 0) ? g_Wqb : (z == 1) ? g_Wkb : g_Wvb;
    __nv_bfloat16* C       = (z == 0) ? g_Q   : (z == 1) ? g_K   : g_V;
    const float scale = (z == 0) ? 0.125f : 1.0f;
    bgemm_body(g_xb, B, C, nullptr, nullptr, 0, scale);
}

__global__ void __launch_bounds__(256) oproj_bgemm_kernel(const float* __restrict__ x,
                                                          float* __restrict__ out)
{
    bgemm_body(g_AO, g_Wob, nullptr, out, x, 2, 1.0f);
}

// ---------------------------------------------------------------------------
// bf16 mma flash attention, 512 thr = 16 warps (8 q-blocks x 2 kv-halves),
// SOFTWARE-PIPELINED ACROSS TILES: iteration j interleaves exp/pack of tile
// j-1 (MUFU/ALU) with S-mma of tile j (tensor), then PV of tile j-1.
// 3-slot K/V ring buffers (V of j-1 must outlive prefetch of j+1).
// Unnormalized streaming softmax (tiles independent, plain accumulation).
// ---------------------------------------------------------------------------
#define A_SW   36
#define A_ROWB 144
#define TS     18432             // one 128x144B tile
#define OQ     0
#define OK     18432             // 3 slots
#define OV     73728             // 3 slots
#define OLS    129024
#define ATT_SMEM (OLS + 1024)

static __device__ __forceinline__ void ld_tile128(uint32_t dst,
                                                  const __nv_bfloat16* src,
                                                  int row0, int tid)
{
#pragma unroll
    for (int i = 0; i < 2; i++) {
        const int idx = tid + i * 512;
        const int r = idx >> 3, c = idx & 7;
        cpa16(dst + r * A_ROWB + c * 16, src + (size_t)(row0 + r) * NDIM + c * 8);
    }
}

// one pipelined step: exp+pack tile J-1 (SOLD) interleaved with S-mma of
// tile J (SNEW), then PV of tile J-1.
#define STEP(SNEW, SOLD, J)                                                  \
{                                                                            \
    cpa_wait0();                                                             \
    __syncthreads();                                                         \
    if ((J) + 1 < NT) {                                                      \
        const int sl = ((J) + 1) % 3;                                        \
        ld_tile128(smb + OK + sl * TS, Kg, ((J) + 1) * 128, tid);            \
        ld_tile128(smb + OV + sl * TS, Vg, ((J) + 1) * 128, tid);            \
        cpa_commit();                                                        \
    }                                                                        \
    const uint32_t* Kw = (const uint32_t*)(smc + OK + ((J) % 3) * TS);       \
    const uint32_t vbase = smb + OV + (((J) - 1) % 3) * TS;                  \
    float rs0 = 0.f, rs1 = 0.f;                                              \
    uint32_t pfr[8][2];                                                      \
    _Pragma("unroll")                                                        \
    for (int ni = 0; ni < 8; ni++) {                                         \
        const float e0 = __expf(SOLD[ni][0]);                                \
        const float e1 = __expf(SOLD[ni][1]);                                \
        const float e2 = __expf(SOLD[ni][2]);                                \
        const float e3 = __expf(SOLD[ni][3]);                                \
        rs0 += e0 + e1; rs1 += e2 + e3;                                      \
        pfr[ni][0] = packbf(e0, e1);                                         \
        pfr[ni][1] = packbf(e2, e3);                                         \
        SNEW[ni][0] = 0.f; SNEW[ni][1] = 0.f;                                \
        SNEW[ni][2] = 0.f; SNEW[ni][3] = 0.f;                                \
        const int br = wc * 64 + ni * 8 + g;                                 \
        _Pragma("unroll")                                                    \
        for (int k4 = 0; k4 < 4; k4++) {                                     \
            const uint32_t b0 = Kw[br * A_SW + k4 * 8 + tc];                 \
            const uint32_t b1 = Kw[br * A_SW + k4 * 8 + tc + 4];             \
            MMA_BF16(SNEW[ni], qfr[k4], b0, b1);                             \
        }                                                                    \
    }                                                                        \
    rs0 += __shfl_xor_sync(0xffffffffu, rs0, 1);                             \
    rs0 += __shfl_xor_sync(0xffffffffu, rs0, 2);                             \
    rs1 += __shfl_xor_sync(0xffffffffu, rs1, 1);                             \
    rs1 += __shfl_xor_sync(0xffffffffu, rs1, 2);                             \
    if (tc == 0) {                                                           \
        ls[wc * 128 + row]     += rs0;                                       \
        ls[wc * 128 + row + 8] += rs1;                                       \
    }                                                                        \
    _Pragma("unroll")                                                        \
    for (int ki = 0; ki < 4; ki++) {                                         \
        uint32_t bfr[8][2];                                                  \
        _Pragma("unroll")                                                    \
        for (int db = 0; db < 4; db++) {                                     \
            const uint32_t addr = vbase +                                    \
                (uint32_t)(wc * 64 + ki * 16 + (mat & 1) * 8 + lr) * A_ROWB +\
                (uint32_t)(db * 16 + (mat >> 1) * 8) * 2;                    \
            LDSM_X4_T(bfr[db * 2][0], bfr[db * 2][1],                        \
                      bfr[db * 2 + 1][0], bfr[db * 2 + 1][1], addr);         \
        }                                                                    \
        uint32_t a[4] = { pfr[2 * ki][0], pfr[2 * ki][1],                    \
                          pfr[2 * ki + 1][0], pfr[2 * ki + 1][1] };          \
        _Pragma("unroll")                                                    \
        for (int nd = 0; nd < 8; nd++)                                       \
            MMA_BF16(oacc[nd], a, bfr[nd][0], bfr[nd][1]);                   \
    }                                                                        \
}

__global__ void __launch_bounds__(512, 1) attn_kernel()
{
    extern __shared__ char smc[];
    const uint32_t smb = s2u(smc);

    const int tid  = threadIdx.x;
    const int wid  = tid >> 5;
    const int lane = tid & 31;
    const int wr = wid & 7;          // q block (16 rows)
    const int wc = wid >> 3;         // kv-half (64 cols)
    const int g  = lane >> 2;
    const int tc = lane & 3;
    const int row = wr * 16 + g;

    const int q0 = blockIdx.x * 128;
    const int bh = blockIdx.y;
    const int b  = bh >> 3;
    const int h  = bh & 7;

    const __nv_bfloat16* Qg = g_Q + (size_t)b * SEQ * NDIM + h * DH;
    const __nv_bfloat16* Kg = g_K + (size_t)b * SEQ * NDIM + h * DH;
    const __nv_bfloat16* Vg = g_V + (size_t)b * SEQ * NDIM + h * DH;

    float* ls = (float*)(smc + OLS);
    if (tid < 256) ls[tid] = 0.f;

    // prologue: Q + tile 0 into slot 0
    ld_tile128(smb + OQ,      Qg, q0, tid);
    ld_tile128(smb + OK,      Kg, 0,  tid);
    ld_tile128(smb + OV,      Vg, 0,  tid);
    cpa_commit();
    cpa_wait0();
    __syncthreads();

    // prefetch tile 1 into slot 1
    ld_tile128(smb + OK + TS, Kg, 128, tid);
    ld_tile128(smb + OV + TS, Vg, 128, tid);
    cpa_commit();

    // hoist Q fragments (4 k16-steps x 4 regs)
    uint32_t qfr[4][4];
    {
        const uint32_t* Qw = (const uint32_t*)smc;
#pragma unroll
        for (int k4 = 0; k4 < 4; k4++) {
            qfr[k4][0] = Qw[row * A_SW + k4 * 8 + tc];
            qfr[k4][1] = Qw[(row + 8) * A_SW + k4 * 8 + tc];
            qfr[k4][2] = Qw[row * A_SW + k4 * 8 + tc + 4];
            qfr[k4][3] = Qw[(row + 8) * A_SW + k4 * 8 + tc + 4];
        }
    }

    float oacc[8][4];
#pragma unroll
    for (int nd = 0; nd < 8; nd++)
#pragma unroll
        for (int c = 0; c < 4; c++) oacc[nd][c] = 0.f;

    const int mat = lane >> 3, lr = lane & 7;

    float sA[8][4], sB[8][4];

    // S_0 (tile 0, slot 0) -> sA
    {
        const uint32_t* Kw = (const uint32_t*)(smc + OK);
#pragma unroll
        for (int ni = 0; ni < 8; ni++) {
            sA[ni][0] = 0.f; sA[ni][1] = 0.f; sA[ni][2] = 0.f; sA[ni][3] = 0.f;
            const int br = wc * 64 + ni * 8 + g;
#pragma unroll
            for (int k4 = 0; k4 < 4; k4++) {
                const uint32_t b0 = Kw[br * A_SW + k4 * 8 + tc];
                const uint32_t b1 = Kw[br * A_SW + k4 * 8 + tc + 4];
                MMA_BF16(sA[ni], qfr[k4], b0, b1);
            }
        }
    }

    // main skewed loop: j = 1 .. NT-1 (NT even -> pairs cover 1..30, then 31)
#pragma unroll 1
    for (int jo = 1; jo + 1 < NT; jo += 2) {
        STEP(sB, sA, jo);
        STEP(sA, sB, jo + 1);
    }
    STEP(sB, sA, NT - 1);

    // drain: exp + PV of tile NT-1 (held in sB, V slot (NT-1)%3)
    {
        const uint32_t vbase = smb + OV + ((NT - 1) % 3) * TS;
        float rs0 = 0.f, rs1 = 0.f;
        uint32_t pfr[8][2];
#pragma unroll
        for (int ni = 0; ni < 8; ni++) {
            const float e0 = __expf(sB[ni][0]);
            const float e1 = __expf(sB[ni][1]);
            const float e2 = __expf(sB[ni][2]);
            const float e3 = __expf(sB[ni][3]);
            rs0 += e0 + e1; rs1 += e2 + e3;
            pfr[ni][0] = packbf(e0, e1);
            pfr[ni][1] = packbf(e2, e3);
        }
        rs0 += __shfl_xor_sync(0xffffffffu, rs0, 1);
        rs0 += __shfl_xor_sync(0xffffffffu, rs0, 2);
        rs1 += __shfl_xor_sync(0xffffffffu, rs1, 1);
        rs1 += __shfl_xor_sync(0xffffffffu, rs1, 2);
        if (tc == 0) {
            ls[wc * 128 + row]     += rs0;
            ls[wc * 128 + row + 8] += rs1;
        }
#pragma unroll
        for (int ki = 0; ki < 4; ki++) {
            uint32_t bfr[8][2];
#pragma unroll
            for (int db = 0; db < 4; db++) {
                const uint32_t addr = vbase +
                    (uint32_t)(wc * 64 + ki * 16 + (mat & 1) * 8 + lr) * A_ROWB +
                    (uint32_t)(db * 16 + (mat >> 1) * 8) * 2;
                LDSM_X4_T(bfr[db * 2][0], bfr[db * 2][1],
                          bfr[db * 2 + 1][0], bfr[db * 2 + 1][1], addr);
            }
            uint32_t a[4] = { pfr[2 * ki][0], pfr[2 * ki][1],
                              pfr[2 * ki + 1][0], pfr[2 * ki + 1][1] };
#pragma unroll
            for (int nd = 0; nd < 8; nd++)
                MMA_BF16(oacc[nd], a, bfr[nd][0], bfr[nd][1]);
        }
    }

    // ---- epilogue: combine kv-halves in smem (reuse K region), store ----
    __syncthreads();
    float* Osm = (float*)(smc + OK);   // 128 x 64, stride 68 floats
    if (wc == 0) {
#pragma unroll
        for (int nd = 0; nd < 8; nd++) {
            const int col = nd * 8 + tc * 2;
            Osm[row * 68 + col]           = oacc[nd][0];
            Osm[row * 68 + col + 1]       = oacc[nd][1];
            Osm[(row + 8) * 68 + col]     = oacc[nd][2];
            Osm[(row + 8) * 68 + col + 1] = oacc[nd][3];
        }
    }
    __syncthreads();
    if (wc == 1) {
#pragma unroll
        for (int nd = 0; nd < 8; nd++) {
            const int col = nd * 8 + tc * 2;
            Osm[row * 68 + col]           += oacc[nd][0];
            Osm[row * 68 + col + 1]       += oacc[nd][1];
            Osm[(row + 8) * 68 + col]     += oacc[nd][2];
            Osm[(row + 8) * 68 + col + 1] += oacc[nd][3];
        }
    }
    __syncthreads();

    const int orow = tid >> 2;
    const int c0   = (tid & 3) * 16;
    const float inv = 1.f / (ls[orow] + ls[128 + orow]);
    __nv_bfloat16* Og = g_AO + (size_t)b * SEQ * NDIM +
                        (size_t)(q0 + orow) * NDIM + h * DH + c0;
#pragma unroll
    for (int c = 0; c < 16; c += 2)
        *(uint32_t*)(Og + c) = packbf(Osm[orow * 68 + c0 + c] * inv,
                                      Osm[orow * 68 + c0 + c + 1] * inv);
}

// ---------------------------------------------------------------------------
extern "C" void kernel_launch(void* const* d_in, const int* in_sizes, int n_in,
                              void* d_out, int out_size)
{
    const float* x  = (const float*)d_in[0];
    const float* Wq = (const float*)d_in[1];
    const float* Wk = (const float*)d_in[2];
    const float* Wv = (const float*)d_in[3];
    const float* Wo = (const float*)d_in[4];
    float* out = (float*)d_out;

    __nv_bfloat16* dxb;
    cudaGetSymbolAddress((void**)&dxb, g_xb);

    cudaFuncSetAttribute(attn_kernel,
                         cudaFuncAttributeMaxDynamicSharedMemorySize, ATT_SMEM);

    cvt_kernel<<<(MTOT * NDIM) / 1024, 256>>>(x, dxb);
    dim3 gw((NDIM * NDIM) / 1024, 1, 4);
    cvtw_kernel<<<gw, 256>>>(Wq, Wk, Wv, Wo);

    dim3 gqkv(NDIM / 128, MTOT / 128, 3);
    qkv_bgemm_kernel<<<gqkv, 256>>>();

    dim3 gattn(SEQ / 128, 16);
    attn_kernel<<<gattn, 512, ATT_SMEM>>>();

    dim3 go(NDIM / 128, MTOT / 128);
    oproj_bgemm_kernel<<<go, 256>>>(x, out);
}

// round 12
// speedup vs baseline: 1.0856x; 1.0856x over previous
#include <cuda_runtime.h>
#include <cuda_bf16.h>
#include <math.h>
#include <stdint.h>

#define MTOT 8192      // 2*4096 rows
#define NDIM 512
#define SEQ  4096
#define DH   64
#define NT   (SEQ / 128)

// scratch (allocation-free rule -> device globals)
__device__ __nv_bfloat16 g_xb [MTOT * NDIM];
__device__ __nv_bfloat16 g_Wqb[NDIM * NDIM];
__device__ __nv_bfloat16 g_Wkb[NDIM * NDIM];
__device__ __nv_bfloat16 g_Wvb[NDIM * NDIM];
__device__ __nv_bfloat16 g_Wob[NDIM * NDIM];
__device__ __nv_bfloat16 g_Q  [MTOT * NDIM];   // pre-scaled x0.125
__device__ __nv_bfloat16 g_K  [MTOT * NDIM];
__device__ __nv_bfloat16 g_V  [MTOT * NDIM];
__device__ __nv_bfloat16 g_AO [MTOT * NDIM];

// ---------------------------------------------------------------------------
// helpers
// ---------------------------------------------------------------------------
static __device__ __forceinline__ uint32_t s2u(const void* p) {
    uint32_t a;
    asm("{ .reg .u64 t; cvta.to.shared.u64 t, %1; cvt.u32.u64 %0, t; }"
        : "=r"(a) : "l"(p));
    return a;
}
static __device__ __forceinline__ uint32_t packbf(float lo, float hi) {
    uint32_t r;
    asm("cvt.rn.bf16x2.f32 %0, %1, %2;" : "=r"(r) : "f"(hi), "f"(lo));
    return r;
}
static __device__ __forceinline__ void cpa16(uint32_t dst, const void* src) {
    asm volatile("cp.async.cg.shared.global [%0], [%1], 16;"
                 :: "r"(dst), "l"(src));
}
static __device__ __forceinline__ void cpa_commit() {
    asm volatile("cp.async.commit_group;" ::: "memory");
}
static __device__ __forceinline__ void cpa_wait0() {
    asm volatile("cp.async.wait_group 0;" ::: "memory");
}

#define MMA_BF16(c, a, b0, b1)                                              \
    asm volatile(                                                           \
        "mma.sync.aligned.m16n8k16.row.col.f32.bf16.bf16.f32 "              \
        "{%0,%1,%2,%3},{%4,%5,%6,%7},{%8,%9},{%0,%1,%2,%3};"                \
        : "+f"((c)[0]), "+f"((c)[1]), "+f"((c)[2]), "+f"((c)[3])            \
        : "r"((a)[0]), "r"((a)[1]), "r"((a)[2]), "r"((a)[3]),               \
          "r"(b0), "r"(b1))

#define LDSM_X4(r0, r1, r2, r3, addr)                                       \
    asm volatile(                                                           \
        "ldmatrix.sync.aligned.m8n8.x4.shared.b16 {%0,%1,%2,%3}, [%4];"     \
        : "=r"(r0), "=r"(r1), "=r"(r2), "=r"(r3) : "r"(addr))

#define LDSM_X4_T(r0, r1, r2, r3, addr)                                     \
    asm volatile(                                                           \
        "ldmatrix.sync.aligned.m8n8.x4.trans.shared.b16 {%0,%1,%2,%3}, [%4];"\
        : "=r"(r0), "=r"(r1), "=r"(r2), "=r"(r3) : "r"(addr))

// ---------------------------------------------------------------------------
// fp32 -> bf16 convert pre-pass (x; and the 4 weights in one launch)
// ---------------------------------------------------------------------------
__global__ void __launch_bounds__(256) cvt_kernel(const float* __restrict__ s,
                                                  __nv_bfloat16* __restrict__ d)
{
    const int i = (blockIdx.x * 256 + threadIdx.x) * 4;
    const float4 v = *(const float4*)(s + i);
    *(uint32_t*)(d + i)     = packbf(v.x, v.y);
    *(uint32_t*)(d + i + 2) = packbf(v.z, v.w);
}

__global__ void __launch_bounds__(256) cvtw_kernel(const float* __restrict__ wq,
                                                   const float* __restrict__ wk,
                                                   const float* __restrict__ wv,
                                                   const float* __restrict__ wo)
{
    const float* s;
    __nv_bfloat16* d;
    switch (blockIdx.z) {
        case 0:  s = wq; d = g_Wqb; break;
        case 1:  s = wk; d = g_Wkb; break;
        case 2:  s = wv; d = g_Wvb; break;
        default: s = wo; d = g_Wob; break;
    }
    const int i = (blockIdx.x * 256 + threadIdx.x) * 4;
    const float4 v = *(const float4*)(s + i);
    *(uint32_t*)(d + i)     = packbf(v.x, v.y);
    *(uint32_t*)(d + i + 2) = packbf(v.z, v.w);
}

// ---------------------------------------------------------------------------
// bf16 GEMM: C[m,n] = sum_k A[m,k] * B[n,k]
// CTA 128x128, kstep 32, 256 thr = 8 warps (4m x 2n), warp 32x64, m16n8k16.
// mode (RUNTIME, epilogue-only): 0 bf16 out (x scale); 2 fp32 out + residual.
// ---------------------------------------------------------------------------
static __device__ __forceinline__ void bgemm_body(
    const __nv_bfloat16* __restrict__ Ag, const __nv_bfloat16* __restrict__ Bg,
    __nv_bfloat16* __restrict__ Cb, float* __restrict__ Cf,
    const float* __restrict__ resid, int mode, float scale)
{
    __shared__ __nv_bfloat16 As[2][128 * 40];
    __shared__ __nv_bfloat16 Bs[2][128 * 40];

    const int tid = threadIdx.x;
    const int wid = tid >> 5, lane = tid & 31;
    const int g = lane >> 2, tc = lane & 3;
    const int wr = wid & 3, wn = wid >> 2;
    const int m0 = blockIdx.y * 128, n0 = blockIdx.x * 128;

    const uint32_t as0 = s2u(As[0]), as1 = s2u(As[1]);
    const uint32_t bs0 = s2u(Bs[0]), bs1 = s2u(Bs[1]);

    {
#pragma unroll
        for (int i = 0; i < 2; i++) {
            const int idx = tid + i * 256;
            const int r = idx >> 2, c = idx & 3;
            cpa16(as0 + r * 80 + c * 16, Ag + (size_t)(m0 + r) * NDIM + c * 8);
            cpa16(bs0 + r * 80 + c * 16, Bg + (size_t)(n0 + r) * NDIM + c * 8);
        }
        cpa_commit();
    }

    float cacc[2][8][4];
#pragma unroll
    for (int mi = 0; mi < 2; mi++)
#pragma unroll
        for (int ni = 0; ni < 8; ni++)
#pragma unroll
            for (int c = 0; c < 4; c++) cacc[mi][ni][c] = 0.f;

    for (int kb = 0; kb < 16; kb++) {
        cpa_wait0();
        __syncthreads();
        if (kb < 15) {
            const int k0 = (kb + 1) * 32;
            const uint32_t as = (kb & 1) ? as0 : as1;
            const uint32_t bs = (kb & 1) ? bs0 : bs1;
#pragma unroll
            for (int i = 0; i < 2; i++) {
                const int idx = tid + i * 256;
                const int r = idx >> 2, c = idx & 3;
                cpa16(as + r * 80 + c * 16, Ag + (size_t)(m0 + r) * NDIM + k0 + c * 8);
                cpa16(bs + r * 80 + c * 16, Bg + (size_t)(n0 + r) * NDIM + k0 + c * 8);
            }
            cpa_commit();
        }
        const uint32_t* Aw = (const uint32_t*)As[kb & 1];
        const uint32_t* Bw = (const uint32_t*)Bs[kb & 1];

#pragma unroll
        for (int h = 0; h < 2; h++) {
            const int kw = h * 8;
            uint32_t a[2][4];
#pragma unroll
            for (int mi = 0; mi < 2; mi++) {
                const int row = wr * 32 + mi * 16 + g;
                a[mi][0] = Aw[row * 20 + kw + tc];
                a[mi][1] = Aw[(row + 8) * 20 + kw + tc];
                a[mi][2] = Aw[row * 20 + kw + tc + 4];
                a[mi][3] = Aw[(row + 8) * 20 + kw + tc + 4];
            }
#pragma unroll
            for (int ni = 0; ni < 8; ni++) {
                const int br = wn * 64 + ni * 8 + g;
                const uint32_t b0 = Bw[br * 20 + kw + tc];
                const uint32_t b1 = Bw[br * 20 + kw + tc + 4];
                MMA_BF16(cacc[0][ni], a[0], b0, b1);
                MMA_BF16(cacc[1][ni], a[1], b0, b1);
            }
        }
    }

#pragma unroll
    for (int mi = 0; mi < 2; mi++) {
        const int row = m0 + wr * 32 + mi * 16 + g;
#pragma unroll
        for (int ni = 0; ni < 8; ni++) {
            const int col = n0 + wn * 64 + ni * 8 + tc * 2;
            if (mode == 2) {
                const float2 x0 = *(const float2*)(resid + (size_t)row * NDIM + col);
                const float2 x1 = *(const float2*)(resid + (size_t)(row + 8) * NDIM + col);
                *(float2*)(Cf + (size_t)row * NDIM + col) =
                    make_float2(cacc[mi][ni][0] + x0.x, cacc[mi][ni][1] + x0.y);
                *(float2*)(Cf + (size_t)(row + 8) * NDIM + col) =
                    make_float2(cacc[mi][ni][2] + x1.x, cacc[mi][ni][3] + x1.y);
            } else {
                *(uint32_t*)(Cb + (size_t)row * NDIM + col) =
                    packbf(cacc[mi][ni][0] * scale, cacc[mi][ni][1] * scale);
                *(uint32_t*)(Cb + (size_t)(row + 8) * NDIM + col) =
                    packbf(cacc[mi][ni][2] * scale, cacc[mi][ni][3] * scale);
            }
        }
    }
}

__global__ void __launch_bounds__(256) qkv_bgemm_kernel()
{
    const int z = blockIdx.z;
    const __nv_bfloat16* B = (z == 0) ? g_Wqb : (z == 1) ? g_Wkb : g_Wvb;
    __nv_bfloat16* C       = (z == 0) ? g_Q   : (z == 1) ? g_K   : g_V;
    const float scale = (z == 0) ? 0.125f : 1.0f;
    bgemm_body(g_xb, B, C, nullptr, nullptr, 0, scale);
}

__global__ void __launch_bounds__(256) oproj_bgemm_kernel(const float* __restrict__ x,
                                                          float* __restrict__ out)
{
    bgemm_body(g_AO, g_Wob, nullptr, out, x, 2, 1.0f);
}

// ---------------------------------------------------------------------------
// bf16 mma flash attention (unnormalized streaming softmax)
// CTA = 128 q x one (b,h), 256 thr = 8 warps (4 q-row x 2 kv-half).
// Warp tile 32q x 64kv (2 warps/SMSP, 256-reg budget -> deep ILP).
// K B-fragments via ldmatrix.x4 (non-trans): 2 ldsm deliver all 8 B-regs
// for one ni (vs 8 scalar LDS), decoupling loads from the mma chain.
// V via ldmatrix.x4.trans. P packed straight from S C-frags.
// smem rows: 128B payload padded to 144B.
// ---------------------------------------------------------------------------
#define A_SW   36
#define A_ROWB 144
#define OQ  0
#define OK0 18432
#define OK1 36864
#define OV0 55296
#define OV1 73728
#define OLS 92160
#define ATT_SMEM (OLS + 1024)

static __device__ __forceinline__ void ld_tile128(uint32_t dst,
                                                  const __nv_bfloat16* src,
                                                  int row0, int tid)
{
#pragma unroll
    for (int i = 0; i < 4; i++) {
        const int idx = tid + i * 256;
        const int r = idx >> 3, c = idx & 7;
        cpa16(dst + r * A_ROWB + c * 16, src + (size_t)(row0 + r) * NDIM + c * 8);
    }
}

__global__ void __launch_bounds__(256, 1) attn_kernel()
{
    extern __shared__ char smc[];
    const uint32_t smb = s2u(smc);

    const int tid  = threadIdx.x;
    const int wid  = tid >> 5;
    const int lane = tid & 31;
    const int wr = wid & 3;          // q-row block (32 rows)
    const int wc = wid >> 2;         // kv-half (64 cols)
    const int g  = lane >> 2;
    const int tc = lane & 3;

    const int q0 = blockIdx.x * 128;
    const int bh = blockIdx.y;
    const int b  = bh >> 3;
    const int h  = bh & 7;

    const __nv_bfloat16* Qg = g_Q + (size_t)b * SEQ * NDIM + h * DH;
    const __nv_bfloat16* Kg = g_K + (size_t)b * SEQ * NDIM + h * DH;
    const __nv_bfloat16* Vg = g_V + (size_t)b * SEQ * NDIM + h * DH;

    float* ls = (float*)(smc + OLS);
    ls[tid] = 0.f;

    ld_tile128(smb + OQ,  Qg, q0, tid);
    ld_tile128(smb + OK0, Kg, 0,  tid);
    ld_tile128(smb + OV0, Vg, 0,  tid);
    cpa_commit();
    cpa_wait0();
    __syncthreads();

    // hoist Q fragments (4 k16-steps x 2 mi x 4 regs)
    uint32_t qfr[4][2][4];
    {
        const uint32_t* Qw = (const uint32_t*)smc;
#pragma unroll
        for (int k4 = 0; k4 < 4; k4++)
#pragma unroll
            for (int mi = 0; mi < 2; mi++) {
                const int row = wr * 32 + mi * 16 + g;
                qfr[k4][mi][0] = Qw[row * A_SW + k4 * 8 + tc];
                qfr[k4][mi][1] = Qw[(row + 8) * A_SW + k4 * 8 + tc];
                qfr[k4][mi][2] = Qw[row * A_SW + k4 * 8 + tc + 4];
                qfr[k4][mi][3] = Qw[(row + 8) * A_SW + k4 * 8 + tc + 4];
            }
    }

    float oacc[2][8][4];
#pragma unroll
    for (int mi = 0; mi < 2; mi++)
#pragma unroll
        for (int nd = 0; nd < 8; nd++)
#pragma unroll
            for (int c = 0; c < 4; c++) oacc[mi][nd][c] = 0.f;

    const int mat = lane >> 3, lr = lane & 7;
    // ldsm.x4 K-frag lane address offset:
    // matrix m = lane>>3: m0=(k4 even, b0), m1=(k4 even, b1),
    //                     m2=(k4 odd,  b0), m3=(k4 odd,  b1)
    // row within matrix = lane&7; per-ni base adds ni*8 rows; 2nd ldsm +64B.
    const uint32_t klane_off =
        (uint32_t)(wc * 64 + lr) * A_ROWB + (uint32_t)((lane >> 4) * 32 + mat % 2 * 16);

    for (int j = 0; j < NT; j++) {
        if (j + 1 < NT) {
            const int nb = (j + 1) & 1;
            ld_tile128(smb + (nb ? OK1 : OK0), Kg, (j + 1) * 128, tid);
            ld_tile128(smb + (nb ? OV1 : OV0), Vg, (j + 1) * 128, tid);
            cpa_commit();
        }

        // ---- S = Q K^T (ldsm.x4 B-frags: 2 ldsm + 8 mma per ni) ----
        const uint32_t kaddr = smb + ((j & 1) ? OK1 : OK0) + klane_off;
        float sacc[2][8][4];
#pragma unroll
        for (int mi = 0; mi < 2; mi++)
#pragma unroll
            for (int ni = 0; ni < 8; ni++)
#pragma unroll
                for (int c = 0; c < 4; c++) sacc[mi][ni][c] = 0.f;

#pragma unroll
        for (int ni = 0; ni < 8; ni++) {
            uint32_t kf[8];
            const uint32_t a0 = kaddr + (uint32_t)(ni * 8) * A_ROWB;
            LDSM_X4(kf[0], kf[1], kf[2], kf[3], a0);        // k4 = 0,1
            LDSM_X4(kf[4], kf[5], kf[6], kf[7], a0 + 64);   // k4 = 2,3
#pragma unroll
            for (int k4 = 0; k4 < 4; k4++) {
                MMA_BF16(sacc[0][ni], qfr[k4][0], kf[k4 * 2], kf[k4 * 2 + 1]);
                MMA_BF16(sacc[1][ni], qfr[k4][1], kf[k4 * 2], kf[k4 * 2 + 1]);
            }
        }

        // ---- softmax (unnormalized): exp, row-sum, pack to bf16 A-frags ----
        uint32_t pfr[2][8][2];
        float rs[2][2] = {{0.f, 0.f}, {0.f, 0.f}};
#pragma unroll
        for (int mi = 0; mi < 2; mi++)
#pragma unroll
            for (int ni = 0; ni < 8; ni++) {
                const float e0 = __expf(sacc[mi][ni][0]);
                const float e1 = __expf(sacc[mi][ni][1]);
                const float e2 = __expf(sacc[mi][ni][2]);
                const float e3 = __expf(sacc[mi][ni][3]);
                rs[mi][0] += e0 + e1;
                rs[mi][1] += e2 + e3;
                pfr[mi][ni][0] = packbf(e0, e1);
                pfr[mi][ni][1] = packbf(e2, e3);
            }
#pragma unroll
        for (int mi = 0; mi < 2; mi++)
#pragma unroll
            for (int hh = 0; hh < 2; hh++) {
                float r = rs[mi][hh];
                r += __shfl_xor_sync(0xffffffffu, r, 1);
                r += __shfl_xor_sync(0xffffffffu, r, 2);
                rs[mi][hh] = r;
            }
        if (tc == 0) {
            float* l = ls + wc * 128 + wr * 32;
#pragma unroll
            for (int mi = 0; mi < 2; mi++) {
                l[mi * 16 + g]     += rs[mi][0];
                l[mi * 16 + 8 + g] += rs[mi][1];
            }
        }

        // ---- O += P V (warp's kv-half, k=64 -> 4 k16-steps) ----
        const uint32_t vbase = smb + ((j & 1) ? OV1 : OV0);
#pragma unroll
        for (int ki = 0; ki < 4; ki++) {
            uint32_t bfr[8][2];
#pragma unroll
            for (int db = 0; db < 4; db++) {
                const uint32_t addr = vbase +
                    (uint32_t)(wc * 64 + ki * 16 + (mat & 1) * 8 + lr) * A_ROWB +
                    (uint32_t)(db * 16 + (mat >> 1) * 8) * 2;
                LDSM_X4_T(bfr[db * 2][0], bfr[db * 2][1],
                          bfr[db * 2 + 1][0], bfr[db * 2 + 1][1], addr);
            }
#pragma unroll
            for (int mi = 0; mi < 2; mi++) {
                uint32_t a[4] = { pfr[mi][2 * ki][0],     pfr[mi][2 * ki][1],
                                  pfr[mi][2 * ki + 1][0], pfr[mi][2 * ki + 1][1] };
#pragma unroll
                for (int nd = 0; nd < 8; nd++)
                    MMA_BF16(oacc[mi][nd], a, bfr[nd][0], bfr[nd][1]);
            }
        }

        if (j + 1 < NT) {
            cpa_wait0();
            __syncthreads();
        }
    }

    // ---- epilogue: combine kv-halves in smem, normalize, store bf16 ----
    __syncthreads();
    float* Osm = (float*)(smc + OK0);   // 128 x 64, stride 68 floats
    if (wc == 0) {
#pragma unroll
        for (int mi = 0; mi < 2; mi++) {
            const int r0 = wr * 32 + mi * 16 + g;
#pragma unroll
            for (int nd = 0; nd < 8; nd++) {
                const int col = nd * 8 + tc * 2;
                Osm[r0 * 68 + col]           = oacc[mi][nd][0];
                Osm[r0 * 68 + col + 1]       = oacc[mi][nd][1];
                Osm[(r0 + 8) * 68 + col]     = oacc[mi][nd][2];
                Osm[(r0 + 8) * 68 + col + 1] = oacc[mi][nd][3];
            }
        }
    }
    __syncthreads();
    if (wc == 1) {
#pragma unroll
        for (int mi = 0; mi < 2; mi++) {
            const int r0 = wr * 32 + mi * 16 + g;
#pragma unroll
            for (int nd = 0; nd < 8; nd++) {
                const int col = nd * 8 + tc * 2;
                Osm[r0 * 68 + col]           += oacc[mi][nd][0];
                Osm[r0 * 68 + col + 1]       += oacc[mi][nd][1];
                Osm[(r0 + 8) * 68 + col]     += oacc[mi][nd][2];
                Osm[(r0 + 8) * 68 + col + 1] += oacc[mi][nd][3];
            }
        }
    }
    __syncthreads();

    const int row = tid >> 1;
    const int c0  = (tid & 1) * 32;
    const float inv = 1.f / (ls[row] + ls[128 + row]);
    __nv_bfloat16* Og = g_AO + (size_t)b * SEQ * NDIM +
                        (size_t)(q0 + row) * NDIM + h * DH + c0;
#pragma unroll
    for (int c = 0; c < 32; c += 2)
        *(uint32_t*)(Og + c) = packbf(Osm[row * 68 + c0 + c] * inv,
                                      Osm[row * 68 + c0 + c + 1] * inv);
}

// ---------------------------------------------------------------------------
extern "C" void kernel_launch(void* const* d_in, const int* in_sizes, int n_in,
                              void* d_out, int out_size)
{
    const float* x  = (const float*)d_in[0];
    const float* Wq = (const float*)d_in[1];
    const float* Wk = (const float*)d_in[2];
    const float* Wv = (const float*)d_in[3];
    const float* Wo = (const float*)d_in[4];
    float* out = (float*)d_out;

    __nv_bfloat16* dxb;
    cudaGetSymbolAddress((void**)&dxb, g_xb);

    cudaFuncSetAttribute(attn_kernel,
                         cudaFuncAttributeMaxDynamicSharedMemorySize, ATT_SMEM);

    cvt_kernel<<<(MTOT * NDIM) / 1024, 256>>>(x, dxb);
    dim3 gw((NDIM * NDIM) / 1024, 1, 4);
    cvtw_kernel<<<gw, 256>>>(Wq, Wk, Wv, Wo);

    dim3 gqkv(NDIM / 128, MTOT / 128, 3);
    qkv_bgemm_kernel<<<gqkv, 256>>>();

    dim3 gattn(SEQ / 128, 16);
    attn_kernel<<<gattn, 256, ATT_SMEM>>>();

    dim3 go(NDIM / 128, MTOT / 128);
    oproj_bgemm_kernel<<<go, 256>>>(x, out);
}

// round 13
// speedup vs baseline: 1.2007x; 1.1061x over previous
#include <cuda_runtime.h>
#include <cuda_bf16.h>
#include <math.h>
#include <stdint.h>

#define MTOT 8192      // 2*4096 rows
#define NDIM 512
#define SEQ  4096
#define DH   64
#define NT   (SEQ / 128)

// scratch (allocation-free rule -> device globals)
__device__ __nv_bfloat16 g_xb [MTOT * NDIM];
__device__ __nv_bfloat16 g_Wqb[NDIM * NDIM];
__device__ __nv_bfloat16 g_Wkb[NDIM * NDIM];
__device__ __nv_bfloat16 g_Wvb[NDIM * NDIM];
__device__ __nv_bfloat16 g_Wob[NDIM * NDIM];
__device__ __nv_bfloat16 g_Q  [MTOT * NDIM];   // pre-scaled x(0.125*log2 e)
__device__ __nv_bfloat16 g_K  [MTOT * NDIM];
__device__ __nv_bfloat16 g_V  [MTOT * NDIM];
__device__ __nv_bfloat16 g_AO [MTOT * NDIM];

// ---------------------------------------------------------------------------
// helpers
// ---------------------------------------------------------------------------
static __device__ __forceinline__ uint32_t s2u(const void* p) {
    uint32_t a;
    asm("{ .reg .u64 t; cvta.to.shared.u64 t, %1; cvt.u32.u64 %0, t; }"
        : "=r"(a) : "l"(p));
    return a;
}
static __device__ __forceinline__ uint32_t packbf(float lo, float hi) {
    uint32_t r;
    asm("cvt.rn.bf16x2.f32 %0, %1, %2;" : "=r"(r) : "f"(hi), "f"(lo));
    return r;
}
static __device__ __forceinline__ float ex2(float x) {
    float y;
    asm("ex2.approx.f32 %0, %1;" : "=f"(y) : "f"(x));
    return y;
}
static __device__ __forceinline__ void cpa16(uint32_t dst, const void* src) {
    asm volatile("cp.async.cg.shared.global [%0], [%1], 16;"
                 :: "r"(dst), "l"(src));
}
static __device__ __forceinline__ void cpa_commit() {
    asm volatile("cp.async.commit_group;" ::: "memory");
}
static __device__ __forceinline__ void cpa_wait0() {
    asm volatile("cp.async.wait_group 0;" ::: "memory");
}

#define MMA_BF16(c, a, b0, b1)                                              \
    asm volatile(                                                           \
        "mma.sync.aligned.m16n8k16.row.col.f32.bf16.bf16.f32 "              \
        "{%0,%1,%2,%3},{%4,%5,%6,%7},{%8,%9},{%0,%1,%2,%3};"                \
        : "+f"((c)[0]), "+f"((c)[1]), "+f"((c)[2]), "+f"((c)[3])            \
        : "r"((a)[0]), "r"((a)[1]), "r"((a)[2]), "r"((a)[3]),               \
          "r"(b0), "r"(b1))

#define LDSM_X4(r0, r1, r2, r3, addr)                                       \
    asm volatile(                                                           \
        "ldmatrix.sync.aligned.m8n8.x4.shared.b16 {%0,%1,%2,%3}, [%4];"     \
        : "=r"(r0), "=r"(r1), "=r"(r2), "=r"(r3) : "r"(addr))

#define LDSM_X4_T(r0, r1, r2, r3, addr)                                     \
    asm volatile(                                                           \
        "ldmatrix.sync.aligned.m8n8.x4.trans.shared.b16 {%0,%1,%2,%3}, [%4];"\
        : "=r"(r0), "=r"(r1), "=r"(r2), "=r"(r3) : "r"(addr))

// ---------------------------------------------------------------------------
// fp32 -> bf16 convert pre-pass (x; and the 4 weights in one launch)
// ---------------------------------------------------------------------------
__global__ void __launch_bounds__(256) cvt_kernel(const float* __restrict__ s,
                                                  __nv_bfloat16* __restrict__ d)
{
    const int i = (blockIdx.x * 256 + threadIdx.x) * 4;
    const float4 v = *(const float4*)(s + i);
    *(uint32_t*)(d + i)     = packbf(v.x, v.y);
    *(uint32_t*)(d + i + 2) = packbf(v.z, v.w);
}

__global__ void __launch_bounds__(256) cvtw_kernel(const float* __restrict__ wq,
                                                   const float* __restrict__ wk,
                                                   const float* __restrict__ wv,
                                                   const float* __restrict__ wo)
{
    const float* s;
    __nv_bfloat16* d;
    switch (blockIdx.z) {
        case 0:  s = wq; d = g_Wqb; break;
        case 1:  s = wk; d = g_Wkb; break;
        case 2:  s = wv; d = g_Wvb; break;
        default: s = wo; d = g_Wob; break;
    }
    const int i = (blockIdx.x * 256 + threadIdx.x) * 4;
    const float4 v = *(const float4*)(s + i);
    *(uint32_t*)(d + i)     = packbf(v.x, v.y);
    *(uint32_t*)(d + i + 2) = packbf(v.z, v.w);
}

// ---------------------------------------------------------------------------
// bf16 GEMM: C[m,n] = sum_k A[m,k] * B[n,k]
// CTA 128x128, kstep 32, 256 thr = 8 warps (4m x 2n), warp 32x64, m16n8k16.
// mode (RUNTIME, epilogue-only): 0 bf16 out (x scale); 2 fp32 out + residual.
// ---------------------------------------------------------------------------
static __device__ __forceinline__ void bgemm_body(
    const __nv_bfloat16* __restrict__ Ag, const __nv_bfloat16* __restrict__ Bg,
    __nv_bfloat16* __restrict__ Cb, float* __restrict__ Cf,
    const float* __restrict__ resid, int mode, float scale)
{
    __shared__ __nv_bfloat16 As[2][128 * 40];
    __shared__ __nv_bfloat16 Bs[2][128 * 40];

    const int tid = threadIdx.x;
    const int wid = tid >> 5, lane = tid & 31;
    const int g = lane >> 2, tc = lane & 3;
    const int wr = wid & 3, wn = wid >> 2;
    const int m0 = blockIdx.y * 128, n0 = blockIdx.x * 128;

    const uint32_t as0 = s2u(As[0]), as1 = s2u(As[1]);
    const uint32_t bs0 = s2u(Bs[0]), bs1 = s2u(Bs[1]);

    {
#pragma unroll
        for (int i = 0; i < 2; i++) {
            const int idx = tid + i * 256;
            const int r = idx >> 2, c = idx & 3;
            cpa16(as0 + r * 80 + c * 16, Ag + (size_t)(m0 + r) * NDIM + c * 8);
            cpa16(bs0 + r * 80 + c * 16, Bg + (size_t)(n0 + r) * NDIM + c * 8);
        }
        cpa_commit();
    }

    float cacc[2][8][4];
#pragma unroll
    for (int mi = 0; mi < 2; mi++)
#pragma unroll
        for (int ni = 0; ni < 8; ni++)
#pragma unroll
            for (int c = 0; c < 4; c++) cacc[mi][ni][c] = 0.f;

    for (int kb = 0; kb < 16; kb++) {
        cpa_wait0();
        __syncthreads();
        if (kb < 15) {
            const int k0 = (kb + 1) * 32;
            const uint32_t as = (kb & 1) ? as0 : as1;
            const uint32_t bs = (kb & 1) ? bs0 : bs1;
#pragma unroll
            for (int i = 0; i < 2; i++) {
                const int idx = tid + i * 256;
                const int r = idx >> 2, c = idx & 3;
                cpa16(as + r * 80 + c * 16, Ag + (size_t)(m0 + r) * NDIM + k0 + c * 8);
                cpa16(bs + r * 80 + c * 16, Bg + (size_t)(n0 + r) * NDIM + k0 + c * 8);
            }
            cpa_commit();
        }
        const uint32_t* Aw = (const uint32_t*)As[kb & 1];
        const uint32_t* Bw = (const uint32_t*)Bs[kb & 1];

#pragma unroll
        for (int h = 0; h < 2; h++) {
            const int kw = h * 8;
            uint32_t a[2][4];
#pragma unroll
            for (int mi = 0; mi < 2; mi++) {
                const int row = wr * 32 + mi * 16 + g;
                a[mi][0] = Aw[row * 20 + kw + tc];
                a[mi][1] = Aw[(row + 8) * 20 + kw + tc];
                a[mi][2] = Aw[row * 20 + kw + tc + 4];
                a[mi][3] = Aw[(row + 8) * 20 + kw + tc + 4];
            }
#pragma unroll
            for (int ni = 0; ni < 8; ni++) {
                const int br = wn * 64 + ni * 8 + g;
                const uint32_t b0 = Bw[br * 20 + kw + tc];
                const uint32_t b1 = Bw[br * 20 + kw + tc + 4];
                MMA_BF16(cacc[0][ni], a[0], b0, b1);
                MMA_BF16(cacc[1][ni], a[1], b0, b1);
            }
        }
    }

#pragma unroll
    for (int mi = 0; mi < 2; mi++) {
        const int row = m0 + wr * 32 + mi * 16 + g;
#pragma unroll
        for (int ni = 0; ni < 8; ni++) {
            const int col = n0 + wn * 64 + ni * 8 + tc * 2;
            if (mode == 2) {
                const float2 x0 = *(const float2*)(resid + (size_t)row * NDIM + col);
                const float2 x1 = *(const float2*)(resid + (size_t)(row + 8) * NDIM + col);
                *(float2*)(Cf + (size_t)row * NDIM + col) =
                    make_float2(cacc[mi][ni][0] + x0.x, cacc[mi][ni][1] + x0.y);
                *(float2*)(Cf + (size_t)(row + 8) * NDIM + col) =
                    make_float2(cacc[mi][ni][2] + x1.x, cacc[mi][ni][3] + x1.y);
            } else {
                *(uint32_t*)(Cb + (size_t)row * NDIM + col) =
                    packbf(cacc[mi][ni][0] * scale, cacc[mi][ni][1] * scale);
                *(uint32_t*)(Cb + (size_t)(row + 8) * NDIM + col) =
                    packbf(cacc[mi][ni][2] * scale, cacc[mi][ni][3] * scale);
            }
        }
    }
}

__global__ void __launch_bounds__(256) qkv_bgemm_kernel()
{
    const int z = blockIdx.z;
    const __nv_bfloat16* B = (z == 0) ? g_Wqb : (z == 1) ? g_Wkb : g_Wvb;
    __nv_bfloat16* C       = (z == 0) ? g_Q   : (z == 1) ? g_K   : g_V;
    const float scale = (z == 0) ? 0.18033688f : 1.0f;   // 0.125 * log2(e)
    bgemm_body(g_xb, B, C, nullptr, nullptr, 0, scale);
}

__global__ void __launch_bounds__(256) oproj_bgemm_kernel(const float* __restrict__ x,
                                                          float* __restrict__ out)
{
    bgemm_body(g_AO, g_Wob, nullptr, out, x, 2, 1.0f);
}

// ---------------------------------------------------------------------------
// bf16 mma flash attention (unnormalized streaming softmax, exp2-folded)
// CTA = 128 q x one (b,h), 256 thr = 8 warps (4 q-row x 2 kv-half).
// PIPE-INTERLEAVED tile body: exp/pack of S-chunk ni-2 is emitted between
// the mma groups of chunk ni; trailing exps + row-sum are woven into the
// PV steps. Keeps tensor and MUFU pipes concurrently busy.
// ---------------------------------------------------------------------------
#define A_SW   36
#define A_ROWB 144
#define OQ  0
#define OK0 18432
#define OK1 36864
#define OV0 55296
#define OV1 73728
#define OLS 92160
#define ATT_SMEM (OLS + 1024)

static __device__ __forceinline__ void ld_tile128(uint32_t dst,
                                                  const __nv_bfloat16* src,
                                                  int row0, int tid)
{
#pragma unroll
    for (int i = 0; i < 4; i++) {
        const int idx = tid + i * 256;
        const int r = idx >> 3, c = idx & 7;
        cpa16(dst + r * A_ROWB + c * 16, src + (size_t)(row0 + r) * NDIM + c * 8);
    }
}

// S-mma for one ni chunk (both mi): 2 ldsm + 8 mma
#define SMMA(ni)                                                             \
{                                                                            \
    uint32_t kf[8];                                                          \
    const uint32_t a0 = kaddr + (uint32_t)((ni) * 8) * A_ROWB;               \
    LDSM_X4(kf[0], kf[1], kf[2], kf[3], a0);                                 \
    LDSM_X4(kf[4], kf[5], kf[6], kf[7], a0 + 64);                            \
    _Pragma("unroll")                                                        \
    for (int k4 = 0; k4 < 4; k4++) {                                         \
        MMA_BF16(sacc[0][ni], qfr[k4][0], kf[k4 * 2], kf[k4 * 2 + 1]);       \
        MMA_BF16(sacc[1][ni], qfr[k4][1], kf[k4 * 2], kf[k4 * 2 + 1]);       \
    }                                                                        \
}

// exp2 + pack + row-sum for one ni chunk (both mi): 8 MUFU + 4 pack
#define EXPP(ni)                                                             \
{                                                                            \
    _Pragma("unroll")                                                        \
    for (int mi = 0; mi < 2; mi++) {                                         \
        const float e0 = ex2(sacc[mi][ni][0]);                               \
        const float e1 = ex2(sacc[mi][ni][1]);                               \
        const float e2 = ex2(sacc[mi][ni][2]);                               \
        const float e3 = ex2(sacc[mi][ni][3]);                               \
        rs[mi][0] += e0 + e1;                                                \
        rs[mi][1] += e2 + e3;                                                \
        pfr[mi][ni][0] = packbf(e0, e1);                                     \
        pfr[mi][ni][1] = packbf(e2, e3);                                     \
    }                                                                        \
}

// PV ldsm block for one ki
#define PVLD(ki)                                                             \
    _Pragma("unroll")                                                        \
    for (int db = 0; db < 4; db++) {                                         \
        const uint32_t addr = vbase +                                        \
            (uint32_t)(wc * 64 + (ki) * 16 + (mat & 1) * 8 + lr) * A_ROWB +  \
            (uint32_t)(db * 16 + (mat >> 1) * 8) * 2;                        \
        LDSM_X4_T(bfr[db * 2][0], bfr[db * 2][1],                            \
                  bfr[db * 2 + 1][0], bfr[db * 2 + 1][1], addr);             \
    }

// PV mma block for one ki
#define PVMMA(ki)                                                            \
    _Pragma("unroll")                                                        \
    for (int mi = 0; mi < 2; mi++) {                                         \
        uint32_t a[4] = { pfr[mi][2 * (ki)][0],     pfr[mi][2 * (ki)][1],    \
                          pfr[mi][2 * (ki) + 1][0], pfr[mi][2 * (ki) + 1][1] };\
        _Pragma("unroll")                                                    \
        for (int nd = 0; nd < 8; nd++)                                       \
            MMA_BF16(oacc[mi][nd], a, bfr[nd][0], bfr[nd][1]);               \
    }

__global__ void __launch_bounds__(256, 1) attn_kernel()
{
    extern __shared__ char smc[];
    const uint32_t smb = s2u(smc);

    const int tid  = threadIdx.x;
    const int wid  = tid >> 5;
    const int lane = tid & 31;
    const int wr = wid & 3;          // q-row block (32 rows)
    const int wc = wid >> 2;         // kv-half (64 cols)
    const int g  = lane >> 2;
    const int tc = lane & 3;

    const int q0 = blockIdx.x * 128;
    const int bh = blockIdx.y;
    const int b  = bh >> 3;
    const int h  = bh & 7;

    const __nv_bfloat16* Qg = g_Q + (size_t)b * SEQ * NDIM + h * DH;
    const __nv_bfloat16* Kg = g_K + (size_t)b * SEQ * NDIM + h * DH;
    const __nv_bfloat16* Vg = g_V + (size_t)b * SEQ * NDIM + h * DH;

    float* ls = (float*)(smc + OLS);
    ls[tid] = 0.f;

    ld_tile128(smb + OQ,  Qg, q0, tid);
    ld_tile128(smb + OK0, Kg, 0,  tid);
    ld_tile128(smb + OV0, Vg, 0,  tid);
    cpa_commit();
    cpa_wait0();
    __syncthreads();

    // hoist Q fragments (4 k16-steps x 2 mi x 4 regs)
    uint32_t qfr[4][2][4];
    {
        const uint32_t* Qw = (const uint32_t*)smc;
#pragma unroll
        for (int k4 = 0; k4 < 4; k4++)
#pragma unroll
            for (int mi = 0; mi < 2; mi++) {
                const int row = wr * 32 + mi * 16 + g;
                qfr[k4][mi][0] = Qw[row * A_SW + k4 * 8 + tc];
                qfr[k4][mi][1] = Qw[(row + 8) * A_SW + k4 * 8 + tc];
                qfr[k4][mi][2] = Qw[row * A_SW + k4 * 8 + tc + 4];
                qfr[k4][mi][3] = Qw[(row + 8) * A_SW + k4 * 8 + tc + 4];
            }
    }

    float oacc[2][8][4];
#pragma unroll
    for (int mi = 0; mi < 2; mi++)
#pragma unroll
        for (int nd = 0; nd < 8; nd++)
#pragma unroll
            for (int c = 0; c < 4; c++) oacc[mi][nd][c] = 0.f;

    const int mat = lane >> 3, lr = lane & 7;
    const uint32_t klane_off =
        (uint32_t)(wc * 64 + lr) * A_ROWB + (uint32_t)((lane >> 4) * 32 + mat % 2 * 16);

    for (int j = 0; j < NT; j++) {
        if (j + 1 < NT) {
            const int nb = (j + 1) & 1;
            ld_tile128(smb + (nb ? OK1 : OK0), Kg, (j + 1) * 128, tid);
            ld_tile128(smb + (nb ? OV1 : OV0), Vg, (j + 1) * 128, tid);
            cpa_commit();
        }

        const uint32_t kaddr = smb + ((j & 1) ? OK1 : OK0) + klane_off;
        const uint32_t vbase = smb + ((j & 1) ? OV1 : OV0);

        float sacc[2][8][4];
#pragma unroll
        for (int mi = 0; mi < 2; mi++)
#pragma unroll
            for (int ni = 0; ni < 8; ni++)
#pragma unroll
                for (int c = 0; c < 4; c++) sacc[mi][ni][c] = 0.f;

        uint32_t pfr[2][8][2];
        float rs[2][2] = {{0.f, 0.f}, {0.f, 0.f}};

        // ---- interleaved S-mma / exp: EXPP(ni-2) woven between SMMA(ni) ----
        SMMA(0) SMMA(1)
        SMMA(2) EXPP(0)
        SMMA(3) EXPP(1)
        SMMA(4) EXPP(2)
        SMMA(5) EXPP(3)
        SMMA(6) EXPP(4)
        SMMA(7) EXPP(5)

        // ---- PV with trailing exps + row-sum woven in ----
        {
            uint32_t bfr[8][2];
            PVLD(0) EXPP(6) PVMMA(0)
            PVLD(1) EXPP(7) PVMMA(1)
            PVLD(2)
            // row-sum reduce + accumulate (once per tile)
#pragma unroll
            for (int mi = 0; mi < 2; mi++)
#pragma unroll
                for (int hh = 0; hh < 2; hh++) {
                    float r = rs[mi][hh];
                    r += __shfl_xor_sync(0xffffffffu, r, 1);
                    r += __shfl_xor_sync(0xffffffffu, r, 2);
                    rs[mi][hh] = r;
                }
            if (tc == 0) {
                float* l = ls + wc * 128 + wr * 32;
#pragma unroll
                for (int mi = 0; mi < 2; mi++) {
                    l[mi * 16 + g]     += rs[mi][0];
                    l[mi * 16 + 8 + g] += rs[mi][1];
                }
            }
            PVMMA(2)
            PVLD(3) PVMMA(3)
        }

        if (j + 1 < NT) {
            cpa_wait0();
            __syncthreads();
        }
    }

    // ---- epilogue: combine kv-halves in smem, normalize, store bf16 ----
    __syncthreads();
    float* Osm = (float*)(smc + OK0);   // 128 x 64, stride 68 floats
    if (wc == 0) {
#pragma unroll
        for (int mi = 0; mi < 2; mi++) {
            const int r0 = wr * 32 + mi * 16 + g;
#pragma unroll
            for (int nd = 0; nd < 8; nd++) {
                const int col = nd * 8 + tc * 2;
                Osm[r0 * 68 + col]           = oacc[mi][nd][0];
                Osm[r0 * 68 + col + 1]       = oacc[mi][nd][1];
                Osm[(r0 + 8) * 68 + col]     = oacc[mi][nd][2];
                Osm[(r0 + 8) * 68 + col + 1] = oacc[mi][nd][3];
            }
        }
    }
    __syncthreads();
    if (wc == 1) {
#pragma unroll
        for (int mi = 0; mi < 2; mi++) {
            const int r0 = wr * 32 + mi * 16 + g;
#pragma unroll
            for (int nd = 0; nd < 8; nd++) {
                const int col = nd * 8 + tc * 2;
                Osm[r0 * 68 + col]           += oacc[mi][nd][0];
                Osm[r0 * 68 + col + 1]       += oacc[mi][nd][1];
                Osm[(r0 + 8) * 68 + col]     += oacc[mi][nd][2];
                Osm[(r0 + 8) * 68 + col + 1] += oacc[mi][nd][3];
            }
        }
    }
    __syncthreads();

    const int row = tid >> 1;
    const int c0  = (tid & 1) * 32;
    const float inv = 1.f / (ls[row] + ls[128 + row]);
    __nv_bfloat16* Og = g_AO + (size_t)b * SEQ * NDIM +
                        (size_t)(q0 + row) * NDIM + h * DH + c0;
#pragma unroll
    for (int c = 0; c < 32; c += 2)
        *(uint32_t*)(Og + c) = packbf(Osm[row * 68 + c0 + c] * inv,
                                      Osm[row * 68 + c0 + c + 1] * inv);
}

// ---------------------------------------------------------------------------
extern "C" void kernel_launch(void* const* d_in, const int* in_sizes, int n_in,
                              void* d_out, int out_size)
{
    const float* x  = (const float*)d_in[0];
    const float* Wq = (const float*)d_in[1];
    const float* Wk = (const float*)d_in[2];
    const float* Wv = (const float*)d_in[3];
    const float* Wo = (const float*)d_in[4];
    float* out = (float*)d_out;

    __nv_bfloat16* dxb;
    cudaGetSymbolAddress((void**)&dxb, g_xb);

    cudaFuncSetAttribute(attn_kernel,
                         cudaFuncAttributeMaxDynamicSharedMemorySize, ATT_SMEM);

    cvt_kernel<<<(MTOT * NDIM) / 1024, 256>>>(x, dxb);
    dim3 gw((NDIM * NDIM) / 1024, 1, 4);
    cvtw_kernel<<<gw, 256>>>(Wq, Wk, Wv, Wo);

    dim3 gqkv(NDIM / 128, MTOT / 128, 3);
    qkv_bgemm_kernel<<<gqkv, 256>>>();

    dim3 gattn(SEQ / 128, 16);
    attn_kernel<<<gattn, 256, ATT_SMEM>>>();

    dim3 go(NDIM / 128, MTOT / 128);
    oproj_bgemm_kernel<<<go, 256>>>(x, out);
}

// round 15
// speedup vs baseline: 1.2284x; 1.0231x over previous
#include <cuda_runtime.h>
#include <cuda_bf16.h>
#include <cuda_fp16.h>
#include <math.h>
#include <stdint.h>

#define MTOT 8192      // 2*4096 rows
#define NDIM 512
#define SEQ  4096
#define DH   64
#define NT   (SEQ / 128)

// scratch (allocation-free rule -> device globals)
__device__ __nv_bfloat16 g_xb [MTOT * NDIM];
__device__ __nv_bfloat16 g_Wqb[NDIM * NDIM];
__device__ __nv_bfloat16 g_Wkb[NDIM * NDIM];
__device__ __nv_bfloat16 g_Wvb[NDIM * NDIM];
__device__ __nv_bfloat16 g_Wob[NDIM * NDIM];
__device__ __nv_bfloat16 g_Q  [MTOT * NDIM];   // pre-scaled x(0.125*log2 e)
__device__ __nv_bfloat16 g_K  [MTOT * NDIM];
__device__ __half        g_V  [MTOT * NDIM];   // fp16 (PV runs fp16 mma)
__device__ __nv_bfloat16 g_AO [MTOT * NDIM];

// ---------------------------------------------------------------------------
// helpers
// ---------------------------------------------------------------------------
static __device__ __forceinline__ uint32_t s2u(const void* p) {
    uint32_t a;
    asm("{ .reg .u64 t; cvta.to.shared.u64 t, %1; cvt.u32.u64 %0, t; }"
        : "=r"(a) : "l"(p));
    return a;
}
static __device__ __forceinline__ uint32_t packbf(float lo, float hi) {
    uint32_t r;
    asm("cvt.rn.bf16x2.f32 %0, %1, %2;" : "=r"(r) : "f"(hi), "f"(lo));
    return r;
}
static __device__ __forceinline__ uint32_t packh(float lo, float hi) {
    uint32_t r;
    asm("cvt.rn.f16x2.f32 %0, %1, %2;" : "=r"(r) : "f"(hi), "f"(lo));
    return r;
}
static __device__ __forceinline__ uint32_t ex2h2(uint32_t v) {
    uint32_t r;
    asm("ex2.approx.f16x2 %0, %1;" : "=r"(r) : "r"(v));
    return r;
}
static __device__ __forceinline__ void cpa16(uint32_t dst, const void* src) {
    asm volatile("cp.async.cg.shared.global [%0], [%1], 16;"
                 :: "r"(dst), "l"(src));
}
static __device__ __forceinline__ void cpa_commit() {
    asm volatile("cp.async.commit_group;" ::: "memory");
}
static __device__ __forceinline__ void cpa_wait0() {
    asm volatile("cp.async.wait_group 0;" ::: "memory");
}

#define MMA_BF16(c, a, b0, b1)                                              \
    asm volatile(                                                           \
        "mma.sync.aligned.m16n8k16.row.col.f32.bf16.bf16.f32 "              \
        "{%0,%1,%2,%3},{%4,%5,%6,%7},{%8,%9},{%0,%1,%2,%3};"                \
        : "+f"((c)[0]), "+f"((c)[1]), "+f"((c)[2]), "+f"((c)[3])            \
        : "r"((a)[0]), "r"((a)[1]), "r"((a)[2]), "r"((a)[3]),               \
          "r"(b0), "r"(b1))

#define MMA_F16(c, a, b0, b1)                                               \
    asm volatile(                                                           \
        "mma.sync.aligned.m16n8k16.row.col.f32.f16.f16.f32 "                \
        "{%0,%1,%2,%3},{%4,%5,%6,%7},{%8,%9},{%0,%1,%2,%3};"                \
        : "+f"((c)[0]), "+f"((c)[1]), "+f"((c)[2]), "+f"((c)[3])            \
        : "r"((a)[0]), "r"((a)[1]), "r"((a)[2]), "r"((a)[3]),               \
          "r"(b0), "r"(b1))

#define LDSM_X4(r0, r1, r2, r3, addr)                                       \
    asm volatile(                                                           \
        "ldmatrix.sync.aligned.m8n8.x4.shared.b16 {%0,%1,%2,%3}, [%4];"     \
        : "=r"(r0), "=r"(r1), "=r"(r2), "=r"(r3) : "r"(addr))

#define LDSM_X4_T(r0, r1, r2, r3, addr)                                     \
    asm volatile(                                                           \
        "ldmatrix.sync.aligned.m8n8.x4.trans.shared.b16 {%0,%1,%2,%3}, [%4];"\
        : "=r"(r0), "=r"(r1), "=r"(r2), "=r"(r3) : "r"(addr))

// ---------------------------------------------------------------------------
// fp32 -> bf16 convert pre-pass (x; and the 4 weights in one launch)
// ---------------------------------------------------------------------------
__global__ void __launch_bounds__(256) cvt_kernel(const float* __restrict__ s,
                                                  __nv_bfloat16* __restrict__ d)
{
    const int i = (blockIdx.x * 256 + threadIdx.x) * 4;
    const float4 v = *(const float4*)(s + i);
    *(uint32_t*)(d + i)     = packbf(v.x, v.y);
    *(uint32_t*)(d + i + 2) = packbf(v.z, v.w);
}

__global__ void __launch_bounds__(256) cvtw_kernel(const float* __restrict__ wq,
                                                   const float* __restrict__ wk,
                                                   const float* __restrict__ wv,
                                                   const float* __restrict__ wo)
{
    const float* s;
    __nv_bfloat16* d;
    switch (blockIdx.z) {
        case 0:  s = wq; d = g_Wqb; break;
        case 1:  s = wk; d = g_Wkb; break;
        case 2:  s = wv; d = g_Wvb; break;
        default: s = wo; d = g_Wob; break;
    }
    const int i = (blockIdx.x * 256 + threadIdx.x) * 4;
    const float4 v = *(const float4*)(s + i);
    *(uint32_t*)(d + i)     = packbf(v.x, v.y);
    *(uint32_t*)(d + i + 2) = packbf(v.z, v.w);
}

// ---------------------------------------------------------------------------
// bf16 GEMM: C[m,n] = sum_k A[m,k] * B[n,k]
// CTA 128x128, kstep 32, 256 thr = 8 warps (4m x 2n), warp 32x64, m16n8k16.
// mode: 0 bf16 out (x scale); 2 fp32 out + residual; 3 fp16 out.
// ---------------------------------------------------------------------------
static __device__ __forceinline__ void bgemm_body(
    const __nv_bfloat16* __restrict__ Ag, const __nv_bfloat16* __restrict__ Bg,
    __nv_bfloat16* __restrict__ Cb, __half* __restrict__ Ch,
    float* __restrict__ Cf, const float* __restrict__ resid,
    int mode, float scale)
{
    __shared__ __nv_bfloat16 As[2][128 * 40];
    __shared__ __nv_bfloat16 Bs[2][128 * 40];

    const int tid = threadIdx.x;
    const int wid = tid >> 5, lane = tid & 31;
    const int g = lane >> 2, tc = lane & 3;
    const int wr = wid & 3, wn = wid >> 2;
    const int m0 = blockIdx.y * 128, n0 = blockIdx.x * 128;

    const uint32_t as0 = s2u(As[0]), as1 = s2u(As[1]);
    const uint32_t bs0 = s2u(Bs[0]), bs1 = s2u(Bs[1]);

    {
#pragma unroll
        for (int i = 0; i < 2; i++) {
            const int idx = tid + i * 256;
            const int r = idx >> 2, c = idx & 3;
            cpa16(as0 + r * 80 + c * 16, Ag + (size_t)(m0 + r) * NDIM + c * 8);
            cpa16(bs0 + r * 80 + c * 16, Bg + (size_t)(n0 + r) * NDIM + c * 8);
        }
        cpa_commit();
    }

    float cacc[2][8][4];
#pragma unroll
    for (int mi = 0; mi < 2; mi++)
#pragma unroll
        for (int ni = 0; ni < 8; ni++)
#pragma unroll
            for (int c = 0; c < 4; c++) cacc[mi][ni][c] = 0.f;

    for (int kb = 0; kb < 16; kb++) {
        cpa_wait0();
        __syncthreads();
        if (kb < 15) {
            const int k0 = (kb + 1) * 32;
            const uint32_t as = (kb & 1) ? as0 : as1;
            const uint32_t bs = (kb & 1) ? bs0 : bs1;
#pragma unroll
            for (int i = 0; i < 2; i++) {
                const int idx = tid + i * 256;
                const int r = idx >> 2, c = idx & 3;
                cpa16(as + r * 80 + c * 16, Ag + (size_t)(m0 + r) * NDIM + k0 + c * 8);
                cpa16(bs + r * 80 + c * 16, Bg + (size_t)(n0 + r) * NDIM + k0 + c * 8);
            }
            cpa_commit();
        }
        const uint32_t* Aw = (const uint32_t*)As[kb & 1];
        const uint32_t* Bw = (const uint32_t*)Bs[kb & 1];

#pragma unroll
        for (int h = 0; h < 2; h++) {
            const int kw = h * 8;
            uint32_t a[2][4];
#pragma unroll
            for (int mi = 0; mi < 2; mi++) {
                const int row = wr * 32 + mi * 16 + g;
                a[mi][0] = Aw[row * 20 + kw + tc];
                a[mi][1] = Aw[(row + 8) * 20 + kw + tc];
                a[mi][2] = Aw[row * 20 + kw + tc + 4];
                a[mi][3] = Aw[(row + 8) * 20 + kw + tc + 4];
            }
#pragma unroll
            for (int ni = 0; ni < 8; ni++) {
                const int br = wn * 64 + ni * 8 + g;
                const uint32_t b0 = Bw[br * 20 + kw + tc];
                const uint32_t b1 = Bw[br * 20 + kw + tc + 4];
                MMA_BF16(cacc[0][ni], a[0], b0, b1);
                MMA_BF16(cacc[1][ni], a[1], b0, b1);
            }
        }
    }

#pragma unroll
    for (int mi = 0; mi < 2; mi++) {
        const int row = m0 + wr * 32 + mi * 16 + g;
#pragma unroll
        for (int ni = 0; ni < 8; ni++) {
            const int col = n0 + wn * 64 + ni * 8 + tc * 2;
            if (mode == 2) {
                const float2 x0 = *(const float2*)(resid + (size_t)row * NDIM + col);
                const float2 x1 = *(const float2*)(resid + (size_t)(row + 8) * NDIM + col);
                *(float2*)(Cf + (size_t)row * NDIM + col) =
                    make_float2(cacc[mi][ni][0] + x0.x, cacc[mi][ni][1] + x0.y);
                *(float2*)(Cf + (size_t)(row + 8) * NDIM + col) =
                    make_float2(cacc[mi][ni][2] + x1.x, cacc[mi][ni][3] + x1.y);
            } else if (mode == 3) {
                *(uint32_t*)(Ch + (size_t)row * NDIM + col) =
                    packh(cacc[mi][ni][0], cacc[mi][ni][1]);
                *(uint32_t*)(Ch + (size_t)(row + 8) * NDIM + col) =
                    packh(cacc[mi][ni][2], cacc[mi][ni][3]);
            } else {
                *(uint32_t*)(Cb + (size_t)row * NDIM + col) =
                    packbf(cacc[mi][ni][0] * scale, cacc[mi][ni][1] * scale);
                *(uint32_t*)(Cb + (size_t)(row + 8) * NDIM + col) =
                    packbf(cacc[mi][ni][2] * scale, cacc[mi][ni][3] * scale);
            }
        }
    }
}

__global__ void __launch_bounds__(256) qkv_bgemm_kernel()
{
    const int z = blockIdx.z;
    if (z == 2) {
        bgemm_body(g_xb, g_Wvb, nullptr, g_V, nullptr, nullptr, 3, 1.0f);
    } else {
        const __nv_bfloat16* B = (z == 0) ? g_Wqb : g_Wkb;
        __nv_bfloat16* C       = (z == 0) ? g_Q   : g_K;
        const float scale = (z == 0) ? 0.18033688f : 1.0f;   // 0.125*log2(e)
        bgemm_body(g_xb, B, C, nullptr, nullptr, nullptr, 0, scale);
    }
}

__global__ void __launch_bounds__(256) oproj_bgemm_kernel(const float* __restrict__ x,
                                                          float* __restrict__ out)
{
    bgemm_body(g_AO, g_Wob, nullptr, nullptr, out, x, 2, 1.0f);
}

// ---------------------------------------------------------------------------
// flash attention: S = QK^T bf16 mma; P = ex2.f16x2 of S (2 exps/MUFU op);
// PV in fp16 mma. Row sums via ones-column in V row padding (col 64 = 1.0h)
// accumulated by the tensor pipe (nd=8 block) -> no FADD/shfl row sums.
// Pipe-interleaved tile body as R13. 256 thr = 8 warps (4 q-row x 2 kv-half).
// ---------------------------------------------------------------------------
#define A_SW   36
#define A_ROWB 144
#define OQ  0
#define OK0 18432
#define OK1 36864
#define OV0 55296
#define OV1 73728
#define OLS 92160
#define ATT_SMEM (OLS + 1024)

static __device__ __forceinline__ void ld_tile128(uint32_t dst,
                                                  const void* src_,
                                                  int row0, int tid)
{
    const __nv_bfloat16* src = (const __nv_bfloat16*)src_;
#pragma unroll
    for (int i = 0; i < 4; i++) {
        const int idx = tid + i * 256;
        const int r = idx >> 3, c = idx & 7;
        cpa16(dst + r * A_ROWB + c * 16, src + (size_t)(row0 + r) * NDIM + c * 8);
    }
}

// S-mma for one ni chunk (both mi): 2 ldsm + 8 mma (bf16)
#define SMMA(ni)                                                             \
{                                                                            \
    uint32_t kf[8];                                                          \
    const uint32_t a0 = kaddr + (uint32_t)((ni) * 8) * A_ROWB;               \
    LDSM_X4(kf[0], kf[1], kf[2], kf[3], a0);                                 \
    LDSM_X4(kf[4], kf[5], kf[6], kf[7], a0 + 64);                            \
    _Pragma("unroll")                                                        \
    for (int k4 = 0; k4 < 4; k4++) {                                         \
        MMA_BF16(sacc[0][ni], qfr[k4][0], kf[k4 * 2], kf[k4 * 2 + 1]);       \
        MMA_BF16(sacc[1][ni], qfr[k4][1], kf[k4 * 2], kf[k4 * 2 + 1]);       \
    }                                                                        \
}

// exp2 in f16x2 for one ni chunk (both mi): 4 cvt + 4 MUFU -> P fp16 frags
#define EXPP(ni)                                                             \
{                                                                            \
    _Pragma("unroll")                                                        \
    for (int mi = 0; mi < 2; mi++) {                                         \
        pfr[mi][ni][0] = ex2h2(packh(sacc[mi][ni][0], sacc[mi][ni][1]));     \
        pfr[mi][ni][1] = ex2h2(packh(sacc[mi][ni][2], sacc[mi][ni][3]));     \
    }                                                                        \
}

// PV ldsm block for one ki: V data (nd 0..7) + ones column (nd 8)
#define PVLD(ki)                                                             \
    _Pragma("unroll")                                                        \
    for (int db = 0; db < 4; db++) {                                         \
        const uint32_t addr = vbase +                                        \
            (uint32_t)(wc * 64 + (ki) * 16 + (mat & 1) * 8 + lr) * A_ROWB +  \
            (uint32_t)(db * 16 + (mat >> 1) * 8) * 2;                        \
        LDSM_X4_T(bfr[db * 2][0], bfr[db * 2][1],                            \
                  bfr[db * 2 + 1][0], bfr[db * 2 + 1][1], addr);             \
    }                                                                        \
    {                                                                        \
        uint32_t dum0, dum1;                                                 \
        const uint32_t addr = vbase +                                        \
            (uint32_t)(wc * 64 + (ki) * 16 + (mat & 1) * 8 + lr) * A_ROWB +  \
            (uint32_t)(64 + (mat >> 1) * 8) * 2;                             \
        LDSM_X4_T(bfr[8][0], bfr[8][1], dum0, dum1, addr);                   \
        (void)dum0; (void)dum1;                                              \
    }

// PV mma block for one ki (fp16), incl. ones block nd=8 (row sums)
#define PVMMA(ki)                                                            \
    _Pragma("unroll")                                                        \
    for (int mi = 0; mi < 2; mi++) {                                         \
        uint32_t a[4] = { pfr[mi][2 * (ki)][0],     pfr[mi][2 * (ki)][1],    \
                          pfr[mi][2 * (ki) + 1][0], pfr[mi][2 * (ki) + 1][1] };\
        _Pragma("unroll")                                                    \
        for (int nd = 0; nd < 9; nd++)                                       \
            MMA_F16(oacc[mi][nd], a, bfr[nd][0], bfr[nd][1]);                \
    }

__global__ void __launch_bounds__(256, 1) attn_kernel()
{
    extern __shared__ char smc[];
    const uint32_t smb = s2u(smc);

    const int tid  = threadIdx.x;
    const int wid  = tid >> 5;
    const int lane = tid & 31;
    const int wr = wid & 3;          // q-row block (32 rows)
    const int wc = wid >> 2;         // kv-half (64 cols)
    const int g  = lane >> 2;
    const int tc = lane & 3;

    const int q0 = blockIdx.x * 128;
    const int bh = blockIdx.y;
    const int b  = bh >> 3;
    const int h  = bh & 7;

    const __nv_bfloat16* Qg = g_Q + (size_t)b * SEQ * NDIM + h * DH;
    const __nv_bfloat16* Kg = g_K + (size_t)b * SEQ * NDIM + h * DH;
    const __half*        Vg = g_V + (size_t)b * SEQ * NDIM + h * DH;

    float* ls = (float*)(smc + OLS);

    ld_tile128(smb + OQ,  Qg, q0, tid);
    ld_tile128(smb + OK0, Kg, 0,  tid);
    ld_tile128(smb + OV0, Vg, 0,  tid);
    cpa_commit();

    // init ones-column pads of BOTH V buffers (col 64 = 1.0h, 65..71 = 0).
    // cp.async only writes the 128B payload; pads persist across tiles.
    {
        const int buf = tid >> 7, r = tid & 127;
        uint32_t pad = smb + (buf ? OV1 : OV0) + (uint32_t)r * A_ROWB + 128;
        uint4 v = make_uint4(0x00003C00u, 0u, 0u, 0u);
        *(uint4*)(smc + (pad - smb)) = v;
    }

    cpa_wait0();
    __syncthreads();

    // hoist Q fragments (4 k16-steps x 2 mi x 4 regs)
    uint32_t qfr[4][2][4];
    {
        const uint32_t* Qw = (const uint32_t*)smc;
#pragma unroll
        for (int k4 = 0; k4 < 4; k4++)
#pragma unroll
            for (int mi = 0; mi < 2; mi++) {
                const int row = wr * 32 + mi * 16 + g;
                qfr[k4][mi][0] = Qw[row * A_SW + k4 * 8 + tc];
                qfr[k4][mi][1] = Qw[(row + 8) * A_SW + k4 * 8 + tc];
                qfr[k4][mi][2] = Qw[row * A_SW + k4 * 8 + tc + 4];
                qfr[k4][mi][3] = Qw[(row + 8) * A_SW + k4 * 8 + tc + 4];
            }
    }

    float oacc[2][9][4];
#pragma unroll
    for (int mi = 0; mi < 2; mi++)
#pragma unroll
        for (int nd = 0; nd < 9; nd++)
#pragma unroll
            for (int c = 0; c < 4; c++) oacc[mi][nd][c] = 0.f;

    const int mat = lane >> 3, lr = lane & 7;
    const uint32_t klane_off =
        (uint32_t)(wc * 64 + lr) * A_ROWB + (uint32_t)((lane >> 4) * 32 + mat % 2 * 16);

    for (int j = 0; j < NT; j++) {
        if (j + 1 < NT) {
            const int nb = (j + 1) & 1;
            ld_tile128(smb + (nb ? OK1 : OK0), Kg, (j + 1) * 128, tid);
            ld_tile128(smb + (nb ? OV1 : OV0), Vg, (j + 1) * 128, tid);
            cpa_commit();
        }

        const uint32_t kaddr = smb + ((j & 1) ? OK1 : OK0) + klane_off;
        const uint32_t vbase = smb + ((j & 1) ? OV1 : OV0);

        float sacc[2][8][4];
#pragma unroll
        for (int mi = 0; mi < 2; mi++)
#pragma unroll
            for (int ni = 0; ni < 8; ni++)
#pragma unroll
                for (int c = 0; c < 4; c++) sacc[mi][ni][c] = 0.f;

        uint32_t pfr[2][8][2];

        // ---- interleaved S-mma / exp ----
        SMMA(0) SMMA(1)
        SMMA(2) EXPP(0)
        SMMA(3) EXPP(1)
        SMMA(4) EXPP(2)
        SMMA(5) EXPP(3)
        SMMA(6) EXPP(4)
        SMMA(7) EXPP(5)

        // ---- PV (fp16) with trailing exps woven in ----
        {
            uint32_t bfr[9][2];
            PVLD(0) EXPP(6) PVMMA(0)
            PVLD(1) EXPP(7) PVMMA(1)
            PVLD(2) PVMMA(2)
            PVLD(3) PVMMA(3)
        }

        if (j + 1 < NT) {
            cpa_wait0();
            __syncthreads();
        }
    }

    // row sums (tensor-computed, col 64 = ones) -> ls
    if (tc == 0) {
        float* l = ls + wc * 128 + wr * 32;
#pragma unroll
        for (int mi = 0; mi < 2; mi++) {
            l[mi * 16 + g]     = oacc[mi][8][0];
            l[mi * 16 + 8 + g] = oacc[mi][8][2];
        }
    }

    // ---- epilogue: combine kv-halves in smem, normalize, store bf16 ----
    __syncthreads();
    float* Osm = (float*)(smc + OK0);   // 128 x 64, stride 68 floats
    if (wc == 0) {
#pragma unroll
        for (int mi = 0; mi < 2; mi++) {
            const int r0 = wr * 32 + mi * 16 + g;
#pragma unroll
            for (int nd = 0; nd < 8; nd++) {
                const int col = nd * 8 + tc * 2;
                Osm[r0 * 68 + col]           = oacc[mi][nd][0];
                Osm[r0 * 68 + col + 1]       = oacc[mi][nd][1];
                Osm[(r0 + 8) * 68 + col]     = oacc[mi][nd][2];
                Osm[(r0 + 8) * 68 + col + 1] = oacc[mi][nd][3];
            }
        }
    }
    __syncthreads();
    if (wc == 1) {
#pragma unroll
        for (int mi = 0; mi < 2; mi++) {
            const int r0 = wr * 32 + mi * 16 + g;
#pragma unroll
            for (int nd = 0; nd < 8; nd++) {
                const int col = nd * 8 + tc * 2;
                Osm[r0 * 68 + col]           += oacc[mi][nd][0];
                Osm[r0 * 68 + col + 1]       += oacc[mi][nd][1];
                Osm[(r0 + 8) * 68 + col]     += oacc[mi][nd][2];
                Osm[(r0 + 8) * 68 + col + 1] += oacc[mi][nd][3];
            }
        }
    }
    __syncthreads();

    const int row = tid >> 1;
    const int c0  = (tid & 1) * 32;
    const float inv = 1.f / (ls[row] + ls[128 + row]);
    __nv_bfloat16* Og = g_AO + (size_t)b * SEQ * NDIM +
                        (size_t)(q0 + row) * NDIM + h * DH + c0;
#pragma unroll
    for (int c = 0; c < 32; c += 2)
        *(uint32_t*)(Og + c) = packbf(Osm[row * 68 + c0 + c] * inv,
                                      Osm[row * 68 + c0 + c + 1] * inv);
}

// ---------------------------------------------------------------------------
extern "C" void kernel_launch(void* const* d_in, const int* in_sizes, int n_in,
                              void* d_out, int out_size)
{
    const float* x  = (const float*)d_in[0];
    const float* Wq = (const float*)d_in[1];
    const float* Wk = (const float*)d_in[2];
    const float* Wv = (const float*)d_in[3];
    const float* Wo = (const float*)d_in[4];
    float* out = (float*)d_out;

    __nv_bfloat16* dxb;
    cudaGetSymbolAddress((void**)&dxb, g_xb);

    cudaFuncSetAttribute(attn_kernel,
                         cudaFuncAttributeMaxDynamicSharedMemorySize, ATT_SMEM);

    cvt_kernel<<<(MTOT * NDIM) / 1024, 256>>>(x, dxb);
    dim3 gw((NDIM * NDIM) / 1024, 1, 4);
    cvtw_kernel<<<gw, 256>>>(Wq, Wk, Wv, Wo);

    dim3 gqkv(NDIM / 128, MTOT / 128, 3);
    qkv_bgemm_kernel<<<gqkv, 256>>>();

    dim3 gattn(SEQ / 128, 16);
    attn_kernel<<<gattn, 256, ATT_SMEM>>>();

    dim3 go(NDIM / 128, MTOT / 128);
    oproj_bgemm_kernel<<<go, 256>>>(x, out);
}

// round 16
// speedup vs baseline: 1.2303x; 1.0015x over previous
#include <cuda_runtime.h>
#include <cuda_bf16.h>
#include <cuda_fp16.h>
#include <math.h>
#include <stdint.h>

#define MTOT 8192      // 2*4096 rows
#define NDIM 512
#define SEQ  4096
#define DH   64
#define NT   (SEQ / 128)

// scratch (allocation-free rule -> device globals)
__device__ __nv_bfloat16 g_xb [MTOT * NDIM];
__device__ __nv_bfloat16 g_Wqb[NDIM * NDIM];
__device__ __nv_bfloat16 g_Wkb[NDIM * NDIM];
__device__ __nv_bfloat16 g_Wvb[NDIM * NDIM];
__device__ __nv_bfloat16 g_Wob[NDIM * NDIM];
__device__ __nv_bfloat16 g_Q  [MTOT * NDIM];   // pre-scaled x(0.125*log2 e)
__device__ __nv_bfloat16 g_K  [MTOT * NDIM];
__device__ __half        g_V  [MTOT * NDIM];   // fp16 (PV runs fp16 mma)
__device__ __nv_bfloat16 g_AO [MTOT * NDIM];

// ---------------------------------------------------------------------------
// helpers
// ---------------------------------------------------------------------------
static __device__ __forceinline__ uint32_t s2u(const void* p) {
    uint32_t a;
    asm("{ .reg .u64 t; cvta.to.shared.u64 t, %1; cvt.u32.u64 %0, t; }"
        : "=r"(a) : "l"(p));
    return a;
}
static __device__ __forceinline__ uint32_t packbf(float lo, float hi) {
    uint32_t r;
    asm("cvt.rn.bf16x2.f32 %0, %1, %2;" : "=r"(r) : "f"(hi), "f"(lo));
    return r;
}
static __device__ __forceinline__ uint32_t packh(float lo, float hi) {
    uint32_t r;
    asm("cvt.rn.f16x2.f32 %0, %1, %2;" : "=r"(r) : "f"(hi), "f"(lo));
    return r;
}
static __device__ __forceinline__ uint32_t ex2h2(uint32_t v) {
    uint32_t r;
    asm("ex2.approx.f16x2 %0, %1;" : "=r"(r) : "r"(v));
    return r;
}
static __device__ __forceinline__ void cpa16(uint32_t dst, const void* src) {
    asm volatile("cp.async.cg.shared.global [%0], [%1], 16;"
                 :: "r"(dst), "l"(src));
}
static __device__ __forceinline__ void cpa_commit() {
    asm volatile("cp.async.commit_group;" ::: "memory");
}
static __device__ __forceinline__ void cpa_wait0() {
    asm volatile("cp.async.wait_group 0;" ::: "memory");
}

#define MMA_BF16(c, a, b0, b1)                                              \
    asm volatile(                                                           \
        "mma.sync.aligned.m16n8k16.row.col.f32.bf16.bf16.f32 "              \
        "{%0,%1,%2,%3},{%4,%5,%6,%7},{%8,%9},{%0,%1,%2,%3};"                \
        : "+f"((c)[0]), "+f"((c)[1]), "+f"((c)[2]), "+f"((c)[3])            \
        : "r"((a)[0]), "r"((a)[1]), "r"((a)[2]), "r"((a)[3]),               \
          "r"(b0), "r"(b1))

#define MMA_F16(c, a, b0, b1)                                               \
    asm volatile(                                                           \
        "mma.sync.aligned.m16n8k16.row.col.f32.f16.f16.f32 "                \
        "{%0,%1,%2,%3},{%4,%5,%6,%7},{%8,%9},{%0,%1,%2,%3};"                \
        : "+f"((c)[0]), "+f"((c)[1]), "+f"((c)[2]), "+f"((c)[3])            \
        : "r"((a)[0]), "r"((a)[1]), "r"((a)[2]), "r"((a)[3]),               \
          "r"(b0), "r"(b1))

#define LDSM_X4(r0, r1, r2, r3, addr)                                       \
    asm volatile(                                                           \
        "ldmatrix.sync.aligned.m8n8.x4.shared.b16 {%0,%1,%2,%3}, [%4];"     \
        : "=r"(r0), "=r"(r1), "=r"(r2), "=r"(r3) : "r"(addr))

#define LDSM_X4_T(r0, r1, r2, r3, addr)                                     \
    asm volatile(                                                           \
        "ldmatrix.sync.aligned.m8n8.x4.trans.shared.b16 {%0,%1,%2,%3}, [%4];"\
        : "=r"(r0), "=r"(r1), "=r"(r2), "=r"(r3) : "r"(addr))

// ---------------------------------------------------------------------------
// fp32 -> bf16 convert pre-pass (x; and the 4 weights in one launch)
// ---------------------------------------------------------------------------
__global__ void __launch_bounds__(256) cvt_kernel(const float* __restrict__ s,
                                                  __nv_bfloat16* __restrict__ d)
{
    const int i = (blockIdx.x * 256 + threadIdx.x) * 4;
    const float4 v = *(const float4*)(s + i);
    *(uint32_t*)(d + i)     = packbf(v.x, v.y);
    *(uint32_t*)(d + i + 2) = packbf(v.z, v.w);
}

__global__ void __launch_bounds__(256) cvtw_kernel(const float* __restrict__ wq,
                                                   const float* __restrict__ wk,
                                                   const float* __restrict__ wv,
                                                   const float* __restrict__ wo)
{
    const float* s;
    __nv_bfloat16* d;
    switch (blockIdx.z) {
        case 0:  s = wq; d = g_Wqb; break;
        case 1:  s = wk; d = g_Wkb; break;
        case 2:  s = wv; d = g_Wvb; break;
        default: s = wo; d = g_Wob; break;
    }
    const int i = (blockIdx.x * 256 + threadIdx.x) * 4;
    const float4 v = *(const float4*)(s + i);
    *(uint32_t*)(d + i)     = packbf(v.x, v.y);
    *(uint32_t*)(d + i + 2) = packbf(v.z, v.w);
}

// ---------------------------------------------------------------------------
// bf16 GEMM: C[m,n] = sum_k A[m,k] * B[n,k]
// CTA 128x128, kstep 32, 256 thr = 8 warps (4m x 2n), warp 32x64, m16n8k16.
// mode: 0 bf16 out (x scale); 2 fp32 out + residual; 3 fp16 out.
// ---------------------------------------------------------------------------
static __device__ __forceinline__ void bgemm_body(
    const __nv_bfloat16* __restrict__ Ag, const __nv_bfloat16* __restrict__ Bg,
    __nv_bfloat16* __restrict__ Cb, __half* __restrict__ Ch,
    float* __restrict__ Cf, const float* __restrict__ resid,
    int mode, float scale)
{
    __shared__ __nv_bfloat16 As[2][128 * 40];
    __shared__ __nv_bfloat16 Bs[2][128 * 40];

    const int tid = threadIdx.x;
    const int wid = tid >> 5, lane = tid & 31;
    const int g = lane >> 2, tc = lane & 3;
    const int wr = wid & 3, wn = wid >> 2;
    const int m0 = blockIdx.y * 128, n0 = blockIdx.x * 128;

    const uint32_t as0 = s2u(As[0]), as1 = s2u(As[1]);
    const uint32_t bs0 = s2u(Bs[0]), bs1 = s2u(Bs[1]);

    {
#pragma unroll
        for (int i = 0; i < 2; i++) {
            const int idx = tid + i * 256;
            const int r = idx >> 2, c = idx & 3;
            cpa16(as0 + r * 80 + c * 16, Ag + (size_t)(m0 + r) * NDIM + c * 8);
            cpa16(bs0 + r * 80 + c * 16, Bg + (size_t)(n0 + r) * NDIM + c * 8);
        }
        cpa_commit();
    }

    float cacc[2][8][4];
#pragma unroll
    for (int mi = 0; mi < 2; mi++)
#pragma unroll
        for (int ni = 0; ni < 8; ni++)
#pragma unroll
            for (int c = 0; c < 4; c++) cacc[mi][ni][c] = 0.f;

    for (int kb = 0; kb < 16; kb++) {
        cpa_wait0();
        __syncthreads();
        if (kb < 15) {
            const int k0 = (kb + 1) * 32;
            const uint32_t as = (kb & 1) ? as0 : as1;
            const uint32_t bs = (kb & 1) ? bs0 : bs1;
#pragma unroll
            for (int i = 0; i < 2; i++) {
                const int idx = tid + i * 256;
                const int r = idx >> 2, c = idx & 3;
                cpa16(as + r * 80 + c * 16, Ag + (size_t)(m0 + r) * NDIM + k0 + c * 8);
                cpa16(bs + r * 80 + c * 16, Bg + (size_t)(n0 + r) * NDIM + k0 + c * 8);
            }
            cpa_commit();
        }
        const uint32_t* Aw = (const uint32_t*)As[kb & 1];
        const uint32_t* Bw = (const uint32_t*)Bs[kb & 1];

#pragma unroll
        for (int h = 0; h < 2; h++) {
            const int kw = h * 8;
            uint32_t a[2][4];
#pragma unroll
            for (int mi = 0; mi < 2; mi++) {
                const int row = wr * 32 + mi * 16 + g;
                a[mi][0] = Aw[row * 20 + kw + tc];
                a[mi][1] = Aw[(row + 8) * 20 + kw + tc];
                a[mi][2] = Aw[row * 20 + kw + tc + 4];
                a[mi][3] = Aw[(row + 8) * 20 + kw + tc + 4];
            }
#pragma unroll
            for (int ni = 0; ni < 8; ni++) {
                const int br = wn * 64 + ni * 8 + g;
                const uint32_t b0 = Bw[br * 20 + kw + tc];
                const uint32_t b1 = Bw[br * 20 + kw + tc + 4];
                MMA_BF16(cacc[0][ni], a[0], b0, b1);
                MMA_BF16(cacc[1][ni], a[1], b0, b1);
            }
        }
    }

#pragma unroll
    for (int mi = 0; mi < 2; mi++) {
        const int row = m0 + wr * 32 + mi * 16 + g;
#pragma unroll
        for (int ni = 0; ni < 8; ni++) {
            const int col = n0 + wn * 64 + ni * 8 + tc * 2;
            if (mode == 2) {
                const float2 x0 = *(const float2*)(resid + (size_t)row * NDIM + col);
                const float2 x1 = *(const float2*)(resid + (size_t)(row + 8) * NDIM + col);
                *(float2*)(Cf + (size_t)row * NDIM + col) =
                    make_float2(cacc[mi][ni][0] + x0.x, cacc[mi][ni][1] + x0.y);
                *(float2*)(Cf + (size_t)(row + 8) * NDIM + col) =
                    make_float2(cacc[mi][ni][2] + x1.x, cacc[mi][ni][3] + x1.y);
            } else if (mode == 3) {
                *(uint32_t*)(Ch + (size_t)row * NDIM + col) =
                    packh(cacc[mi][ni][0], cacc[mi][ni][1]);
                *(uint32_t*)(Ch + (size_t)(row + 8) * NDIM + col) =
                    packh(cacc[mi][ni][2], cacc[mi][ni][3]);
            } else {
                *(uint32_t*)(Cb + (size_t)row * NDIM + col) =
                    packbf(cacc[mi][ni][0] * scale, cacc[mi][ni][1] * scale);
                *(uint32_t*)(Cb + (size_t)(row + 8) * NDIM + col) =
                    packbf(cacc[mi][ni][2] * scale, cacc[mi][ni][3] * scale);
            }
        }
    }
}

__global__ void __launch_bounds__(256) qkv_bgemm_kernel()
{
    const int z = blockIdx.z;
    if (z == 2) {
        bgemm_body(g_xb, g_Wvb, nullptr, g_V, nullptr, nullptr, 3, 1.0f);
    } else {
        const __nv_bfloat16* B = (z == 0) ? g_Wqb : g_Wkb;
        __nv_bfloat16* C       = (z == 0) ? g_Q   : g_K;
        const float scale = (z == 0) ? 0.18033688f : 1.0f;   // 0.125*log2(e)
        bgemm_body(g_xb, B, C, nullptr, nullptr, nullptr, 0, scale);
    }
}

__global__ void __launch_bounds__(256) oproj_bgemm_kernel(const float* __restrict__ x,
                                                          float* __restrict__ out)
{
    bgemm_body(g_AO, g_Wob, nullptr, nullptr, out, x, 2, 1.0f);
}

// ---------------------------------------------------------------------------
// flash attention: S = QK^T bf16 mma (ni-PAIRED: 4 independent accumulator
// chains per warp in flight); P = ex2.f16x2; PV fp16 mma with ones-column
// row sums on the tensor pipe. 256 thr = 8 warps (4 q-row x 2 kv-half).
// ---------------------------------------------------------------------------
#define A_SW   36
#define A_ROWB 144
#define OQ  0
#define OK0 18432
#define OK1 36864
#define OV0 55296
#define OV1 73728
#define OLS 92160
#define ATT_SMEM (OLS + 1024)

static __device__ __forceinline__ void ld_tile128(uint32_t dst,
                                                  const void* src_,
                                                  int row0, int tid)
{
    const __nv_bfloat16* src = (const __nv_bfloat16*)src_;
#pragma unroll
    for (int i = 0; i < 4; i++) {
        const int idx = tid + i * 256;
        const int r = idx >> 3, c = idx & 7;
        cpa16(dst + r * A_ROWB + c * 16, src + (size_t)(row0 + r) * NDIM + c * 8);
    }
}

// S-mma for an ni PAIR: 4 ldsm up front, then 16 mma round-robined across
// 4 independent accumulator chains (2 mi x 2 ni).
#define SMMA2(ni0, ni1)                                                      \
{                                                                            \
    uint32_t kfa[8], kfb[8];                                                 \
    const uint32_t a0 = kaddr + (uint32_t)((ni0) * 8) * A_ROWB;              \
    const uint32_t a1 = kaddr + (uint32_t)((ni1) * 8) * A_ROWB;              \
    LDSM_X4(kfa[0], kfa[1], kfa[2], kfa[3], a0);                             \
    LDSM_X4(kfa[4], kfa[5], kfa[6], kfa[7], a0 + 64);                        \
    LDSM_X4(kfb[0], kfb[1], kfb[2], kfb[3], a1);                             \
    LDSM_X4(kfb[4], kfb[5], kfb[6], kfb[7], a1 + 64);                        \
    _Pragma("unroll")                                                        \
    for (int k4 = 0; k4 < 4; k4++) {                                         \
        MMA_BF16(sacc[0][ni0], qfr[k4][0], kfa[k4 * 2], kfa[k4 * 2 + 1]);    \
        MMA_BF16(sacc[1][ni0], qfr[k4][1], kfa[k4 * 2], kfa[k4 * 2 + 1]);    \
        MMA_BF16(sacc[0][ni1], qfr[k4][0], kfb[k4 * 2], kfb[k4 * 2 + 1]);    \
        MMA_BF16(sacc[1][ni1], qfr[k4][1], kfb[k4 * 2], kfb[k4 * 2 + 1]);    \
    }                                                                        \
}

// exp2 in f16x2 for one ni chunk (both mi): 4 cvt + 4 MUFU -> P fp16 frags
#define EXPP(ni)                                                             \
{                                                                            \
    _Pragma("unroll")                                                        \
    for (int mi = 0; mi < 2; mi++) {                                         \
        pfr[mi][ni][0] = ex2h2(packh(sacc[mi][ni][0], sacc[mi][ni][1]));     \
        pfr[mi][ni][1] = ex2h2(packh(sacc[mi][ni][2], sacc[mi][ni][3]));     \
    }                                                                        \
}

// PV ldsm block for one ki: V data (nd 0..7) + ones column (nd 8)
#define PVLD(ki)                                                             \
    _Pragma("unroll")                                                        \
    for (int db = 0; db < 4; db++) {                                         \
        const uint32_t addr = vbase +                                        \
            (uint32_t)(wc * 64 + (ki) * 16 + (mat & 1) * 8 + lr) * A_ROWB +  \
            (uint32_t)(db * 16 + (mat >> 1) * 8) * 2;                        \
        LDSM_X4_T(bfr[db * 2][0], bfr[db * 2][1],                            \
                  bfr[db * 2 + 1][0], bfr[db * 2 + 1][1], addr);             \
    }                                                                        \
    {                                                                        \
        uint32_t dum0, dum1;                                                 \
        const uint32_t addr = vbase +                                        \
            (uint32_t)(wc * 64 + (ki) * 16 + (mat & 1) * 8 + lr) * A_ROWB +  \
            (uint32_t)(64 + (mat >> 1) * 8) * 2;                             \
        LDSM_X4_T(bfr[8][0], bfr[8][1], dum0, dum1, addr);                   \
        (void)dum0; (void)dum1;                                              \
    }

// PV mma block for one ki (fp16), incl. ones block nd=8 (row sums)
#define PVMMA(ki)                                                            \
    _Pragma("unroll")                                                        \
    for (int mi = 0; mi < 2; mi++) {                                         \
        uint32_t a[4] = { pfr[mi][2 * (ki)][0],     pfr[mi][2 * (ki)][1],    \
                          pfr[mi][2 * (ki) + 1][0], pfr[mi][2 * (ki) + 1][1] };\
        _Pragma("unroll")                                                    \
        for (int nd = 0; nd < 9; nd++)                                       \
            MMA_F16(oacc[mi][nd], a, bfr[nd][0], bfr[nd][1]);                \
    }

__global__ void __launch_bounds__(256, 1) attn_kernel()
{
    extern __shared__ char smc[];
    const uint32_t smb = s2u(smc);

    const int tid  = threadIdx.x;
    const int wid  = tid >> 5;
    const int lane = tid & 31;
    const int wr = wid & 3;          // q-row block (32 rows)
    const int wc = wid >> 2;         // kv-half (64 cols)
    const int g  = lane >> 2;
    const int tc = lane & 3;

    const int q0 = blockIdx.x * 128;
    const int bh = blockIdx.y;
    const int b  = bh >> 3;
    const int h  = bh & 7;

    const __nv_bfloat16* Qg = g_Q + (size_t)b * SEQ * NDIM + h * DH;
    const __nv_bfloat16* Kg = g_K + (size_t)b * SEQ * NDIM + h * DH;
    const __half*        Vg = g_V + (size_t)b * SEQ * NDIM + h * DH;

    float* ls = (float*)(smc + OLS);

    ld_tile128(smb + OQ,  Qg, q0, tid);
    ld_tile128(smb + OK0, Kg, 0,  tid);
    ld_tile128(smb + OV0, Vg, 0,  tid);
    cpa_commit();

    // init ones-column pads of BOTH V buffers (col 64 = 1.0h, 65..71 = 0).
    {
        const int buf = tid >> 7, r = tid & 127;
        uint32_t pad = smb + (buf ? OV1 : OV0) + (uint32_t)r * A_ROWB + 128;
        uint4 v = make_uint4(0x00003C00u, 0u, 0u, 0u);
        *(uint4*)(smc + (pad - smb)) = v;
    }

    cpa_wait0();
    __syncthreads();

    // hoist Q fragments (4 k16-steps x 2 mi x 4 regs)
    uint32_t qfr[4][2][4];
    {
        const uint32_t* Qw = (const uint32_t*)smc;
#pragma unroll
        for (int k4 = 0; k4 < 4; k4++)
#pragma unroll
            for (int mi = 0; mi < 2; mi++) {
                const int row = wr * 32 + mi * 16 + g;
                qfr[k4][mi][0] = Qw[row * A_SW + k4 * 8 + tc];
                qfr[k4][mi][1] = Qw[(row + 8) * A_SW + k4 * 8 + tc];
                qfr[k4][mi][2] = Qw[row * A_SW + k4 * 8 + tc + 4];
                qfr[k4][mi][3] = Qw[(row + 8) * A_SW + k4 * 8 + tc + 4];
            }
    }

    float oacc[2][9][4];
#pragma unroll
    for (int mi = 0; mi < 2; mi++)
#pragma unroll
        for (int nd = 0; nd < 9; nd++)
#pragma unroll
            for (int c = 0; c < 4; c++) oacc[mi][nd][c] = 0.f;

    const int mat = lane >> 3, lr = lane & 7;
    const uint32_t klane_off =
        (uint32_t)(wc * 64 + lr) * A_ROWB + (uint32_t)((lane >> 4) * 32 + mat % 2 * 16);

    for (int j = 0; j < NT; j++) {
        if (j + 1 < NT) {
            const int nb = (j + 1) & 1;
            ld_tile128(smb + (nb ? OK1 : OK0), Kg, (j + 1) * 128, tid);
            ld_tile128(smb + (nb ? OV1 : OV0), Vg, (j + 1) * 128, tid);
            cpa_commit();
        }

        const uint32_t kaddr = smb + ((j & 1) ? OK1 : OK0) + klane_off;
        const uint32_t vbase = smb + ((j & 1) ? OV1 : OV0);

        float sacc[2][8][4];
#pragma unroll
        for (int mi = 0; mi < 2; mi++)
#pragma unroll
            for (int ni = 0; ni < 8; ni++)
#pragma unroll
                for (int c = 0; c < 4; c++) sacc[mi][ni][c] = 0.f;

        uint32_t pfr[2][8][2];

        // ---- ni-paired S-mma with exp woven between pairs ----
        SMMA2(0, 1)
        SMMA2(2, 3) EXPP(0)
        SMMA2(4, 5) EXPP(1) EXPP(2)
        SMMA2(6, 7) EXPP(3) EXPP(4)

        // ---- PV (fp16) with trailing exps woven in ----
        {
            uint32_t bfr[9][2];
            PVLD(0) EXPP(5) PVMMA(0)
            PVLD(1) EXPP(6) PVMMA(1)
            PVLD(2) EXPP(7) PVMMA(2)
            PVLD(3) PVMMA(3)
        }

        if (j + 1 < NT) {
            cpa_wait0();
            __syncthreads();
        }
    }

    // row sums (tensor-computed, col 64 = ones) -> ls
    if (tc == 0) {
        float* l = ls + wc * 128 + wr * 32;
#pragma unroll
        for (int mi = 0; mi < 2; mi++) {
            l[mi * 16 + g]     = oacc[mi][8][0];
            l[mi * 16 + 8 + g] = oacc[mi][8][2];
        }
    }

    // ---- epilogue: combine kv-halves in smem, normalize, store bf16 ----
    __syncthreads();
    float* Osm = (float*)(smc + OK0);   // 128 x 64, stride 68 floats
    if (wc == 0) {
#pragma unroll
        for (int mi = 0; mi < 2; mi++) {
            const int r0 = wr * 32 + mi * 16 + g;
#pragma unroll
            for (int nd = 0; nd < 8; nd++) {
                const int col = nd * 8 + tc * 2;
                Osm[r0 * 68 + col]           = oacc[mi][nd][0];
                Osm[r0 * 68 + col + 1]       = oacc[mi][nd][1];
                Osm[(r0 + 8) * 68 + col]     = oacc[mi][nd][2];
                Osm[(r0 + 8) * 68 + col + 1] = oacc[mi][nd][3];
            }
        }
    }
    __syncthreads();
    if (wc == 1) {
#pragma unroll
        for (int mi = 0; mi < 2; mi++) {
            const int r0 = wr * 32 + mi * 16 + g;
#pragma unroll
            for (int nd = 0; nd < 8; nd++) {
                const int col = nd * 8 + tc * 2;
                Osm[r0 * 68 + col]           += oacc[mi][nd][0];
                Osm[r0 * 68 + col + 1]       += oacc[mi][nd][1];
                Osm[(r0 + 8) * 68 + col]     += oacc[mi][nd][2];
                Osm[(r0 + 8) * 68 + col + 1] += oacc[mi][nd][3];
            }
        }
    }
    __syncthreads();

    const int row = tid >> 1;
    const int c0  = (tid & 1) * 32;
    const float inv = 1.f / (ls[row] + ls[128 + row]);
    __nv_bfloat16* Og = g_AO + (size_t)b * SEQ * NDIM +
                        (size_t)(q0 + row) * NDIM + h * DH + c0;
#pragma unroll
    for (int c = 0; c < 32; c += 2)
        *(uint32_t*)(Og + c) = packbf(Osm[row * 68 + c0 + c] * inv,
                                      Osm[row * 68 + c0 + c + 1] * inv);
}

// ---------------------------------------------------------------------------
extern "C" void kernel_launch(void* const* d_in, const int* in_sizes, int n_in,
                              void* d_out, int out_size)
{
    const float* x  = (const float*)d_in[0];
    const float* Wq = (const float*)d_in[1];
    const float* Wk = (const float*)d_in[2];
    const float* Wv = (const float*)d_in[3];
    const float* Wo = (const float*)d_in[4];
    float* out = (float*)d_out;

    __nv_bfloat16* dxb;
    cudaGetSymbolAddress((void**)&dxb, g_xb);

    cudaFuncSetAttribute(attn_kernel,
                         cudaFuncAttributeMaxDynamicSharedMemorySize, ATT_SMEM);

    cvt_kernel<<<(MTOT * NDIM) / 1024, 256>>>(x, dxb);
    dim3 gw((NDIM * NDIM) / 1024, 1, 4);
    cvtw_kernel<<<gw, 256>>>(Wq, Wk, Wv, Wo);

    dim3 gqkv(NDIM / 128, MTOT / 128, 3);
    qkv_bgemm_kernel<<<gqkv, 256>>>();

    dim3 gattn(SEQ / 128, 16);
    attn_kernel<<<gattn, 256, ATT_SMEM>>>();

    dim3 go(NDIM / 128, MTOT / 128);
    oproj_bgemm_kernel<<<go, 256>>>(x, out);
}

// round 17
// speedup vs baseline: 1.2759x; 1.0370x over previous
#include <cuda_runtime.h>
#include <cuda_bf16.h>
#include <cuda_fp16.h>
#include <math.h>
#include <stdint.h>

#define MTOT 8192      // 2*4096 rows
#define NDIM 512
#define SEQ  4096
#define DH   64
#define NT   (SEQ / 128)

// scratch (allocation-free rule -> device globals)
__device__ __nv_bfloat16 g_xb [MTOT * NDIM];
__device__ __nv_bfloat16 g_Wqb[NDIM * NDIM];
__device__ __nv_bfloat16 g_Wkb[NDIM * NDIM];
__device__ __nv_bfloat16 g_Wvb[NDIM * NDIM];
__device__ __nv_bfloat16 g_Wob[NDIM * NDIM];
__device__ __nv_bfloat16 g_Q  [MTOT * NDIM];   // pre-scaled x(0.125*log2 e)
__device__ __nv_bfloat16 g_K  [MTOT * NDIM];
__device__ __half        g_V  [MTOT * NDIM];   // fp16 (PV runs fp16 mma)
__device__ __nv_bfloat16 g_AO [MTOT * NDIM];

// ---------------------------------------------------------------------------
// helpers
// ---------------------------------------------------------------------------
static __device__ __forceinline__ uint32_t s2u(const void* p) {
    uint32_t a;
    asm("{ .reg .u64 t; cvta.to.shared.u64 t, %1; cvt.u32.u64 %0, t; }"
        : "=r"(a) : "l"(p));
    return a;
}
static __device__ __forceinline__ uint32_t packbf(float lo, float hi) {
    uint32_t r;
    asm("cvt.rn.bf16x2.f32 %0, %1, %2;" : "=r"(r) : "f"(hi), "f"(lo));
    return r;
}
static __device__ __forceinline__ uint32_t packh(float lo, float hi) {
    uint32_t r;
    asm("cvt.rn.f16x2.f32 %0, %1, %2;" : "=r"(r) : "f"(hi), "f"(lo));
    return r;
}
static __device__ __forceinline__ uint32_t ex2h2(uint32_t v) {
    uint32_t r;
    asm("ex2.approx.f16x2 %0, %1;" : "=r"(r) : "r"(v));
    return r;
}
static __device__ __forceinline__ void cpa16(uint32_t dst, const void* src) {
    asm volatile("cp.async.cg.shared.global [%0], [%1], 16;"
                 :: "r"(dst), "l"(src));
}
static __device__ __forceinline__ void cpa_commit() {
    asm volatile("cp.async.commit_group;" ::: "memory");
}
static __device__ __forceinline__ void cpa_wait0() {
    asm volatile("cp.async.wait_group 0;" ::: "memory");
}

#define MMA_BF16(c, a, b0, b1)                                              \
    asm volatile(                                                           \
        "mma.sync.aligned.m16n8k16.row.col.f32.bf16.bf16.f32 "              \
        "{%0,%1,%2,%3},{%4,%5,%6,%7},{%8,%9},{%0,%1,%2,%3};"                \
        : "+f"((c)[0]), "+f"((c)[1]), "+f"((c)[2]), "+f"((c)[3])            \
        : "r"((a)[0]), "r"((a)[1]), "r"((a)[2]), "r"((a)[3]),               \
          "r"(b0), "r"(b1))

#define MMA_F16(c, a, b0, b1)                                               \
    asm volatile(                                                           \
        "mma.sync.aligned.m16n8k16.row.col.f32.f16.f16.f32 "                \
        "{%0,%1,%2,%3},{%4,%5,%6,%7},{%8,%9},{%0,%1,%2,%3};"                \
        : "+f"((c)[0]), "+f"((c)[1]), "+f"((c)[2]), "+f"((c)[3])            \
        : "r"((a)[0]), "r"((a)[1]), "r"((a)[2]), "r"((a)[3]),               \
          "r"(b0), "r"(b1))

#define LDSM_X4(r0, r1, r2, r3, addr)                                       \
    asm volatile(                                                           \
        "ldmatrix.sync.aligned.m8n8.x4.shared.b16 {%0,%1,%2,%3}, [%4];"     \
        : "=r"(r0), "=r"(r1), "=r"(r2), "=r"(r3) : "r"(addr))

#define LDSM_X4_T(r0, r1, r2, r3, addr)                                     \
    asm volatile(                                                           \
        "ldmatrix.sync.aligned.m8n8.x4.trans.shared.b16 {%0,%1,%2,%3}, [%4];"\
        : "=r"(r0), "=r"(r1), "=r"(r2), "=r"(r3) : "r"(addr))

// ---------------------------------------------------------------------------
// fp32 -> bf16 convert pre-pass (x; and the 4 weights in one launch)
// ---------------------------------------------------------------------------
__global__ void __launch_bounds__(256) cvt_kernel(const float* __restrict__ s,
                                                  __nv_bfloat16* __restrict__ d)
{
    const int i = (blockIdx.x * 256 + threadIdx.x) * 4;
    const float4 v = *(const float4*)(s + i);
    *(uint32_t*)(d + i)     = packbf(v.x, v.y);
    *(uint32_t*)(d + i + 2) = packbf(v.z, v.w);
}

__global__ void __launch_bounds__(256) cvtw_kernel(const float* __restrict__ wq,
                                                   const float* __restrict__ wk,
                                                   const float* __restrict__ wv,
                                                   const float* __restrict__ wo)
{
    const float* s;
    __nv_bfloat16* d;
    switch (blockIdx.z) {
        case 0:  s = wq; d = g_Wqb; break;
        case 1:  s = wk; d = g_Wkb; break;
        case 2:  s = wv; d = g_Wvb; break;
        default: s = wo; d = g_Wob; break;
    }
    const int i = (blockIdx.x * 256 + threadIdx.x) * 4;
    const float4 v = *(const float4*)(s + i);
    *(uint32_t*)(d + i)     = packbf(v.x, v.y);
    *(uint32_t*)(d + i + 2) = packbf(v.z, v.w);
}

// ---------------------------------------------------------------------------
// bf16 GEMM: C[m,n] = sum_k A[m,k] * B[n,k]
// CTA 128x128, kstep 32, 256 thr = 8 warps (4m x 2n), warp 32x64, m16n8k16.
// mode: 0 bf16 out (x scale); 2 fp32 out + residual; 3 fp16 out.
// ---------------------------------------------------------------------------
static __device__ __forceinline__ void bgemm_body(
    const __nv_bfloat16* __restrict__ Ag, const __nv_bfloat16* __restrict__ Bg,
    __nv_bfloat16* __restrict__ Cb, __half* __restrict__ Ch,
    float* __restrict__ Cf, const float* __restrict__ resid,
    int mode, float scale)
{
    __shared__ __nv_bfloat16 As[2][128 * 40];
    __shared__ __nv_bfloat16 Bs[2][128 * 40];

    const int tid = threadIdx.x;
    const int wid = tid >> 5, lane = tid & 31;
    const int g = lane >> 2, tc = lane & 3;
    const int wr = wid & 3, wn = wid >> 2;
    const int m0 = blockIdx.y * 128, n0 = blockIdx.x * 128;

    const uint32_t as0 = s2u(As[0]), as1 = s2u(As[1]);
    const uint32_t bs0 = s2u(Bs[0]), bs1 = s2u(Bs[1]);

    {
#pragma unroll
        for (int i = 0; i < 2; i++) {
            const int idx = tid + i * 256;
            const int r = idx >> 2, c = idx & 3;
            cpa16(as0 + r * 80 + c * 16, Ag + (size_t)(m0 + r) * NDIM + c * 8);
            cpa16(bs0 + r * 80 + c * 16, Bg + (size_t)(n0 + r) * NDIM + c * 8);
        }
        cpa_commit();
    }

    float cacc[2][8][4];
#pragma unroll
    for (int mi = 0; mi < 2; mi++)
#pragma unroll
        for (int ni = 0; ni < 8; ni++)
#pragma unroll
            for (int c = 0; c < 4; c++) cacc[mi][ni][c] = 0.f;

    for (int kb = 0; kb < 16; kb++) {
        cpa_wait0();
        __syncthreads();
        if (kb < 15) {
            const int k0 = (kb + 1) * 32;
            const uint32_t as = (kb & 1) ? as0 : as1;
            const uint32_t bs = (kb & 1) ? bs0 : bs1;
#pragma unroll
            for (int i = 0; i < 2; i++) {
                const int idx = tid + i * 256;
                const int r = idx >> 2, c = idx & 3;
                cpa16(as + r * 80 + c * 16, Ag + (size_t)(m0 + r) * NDIM + k0 + c * 8);
                cpa16(bs + r * 80 + c * 16, Bg + (size_t)(n0 + r) * NDIM + k0 + c * 8);
            }
            cpa_commit();
        }
        const uint32_t* Aw = (const uint32_t*)As[kb & 1];
        const uint32_t* Bw = (const uint32_t*)Bs[kb & 1];

#pragma unroll
        for (int h = 0; h < 2; h++) {
            const int kw = h * 8;
            uint32_t a[2][4];
#pragma unroll
            for (int mi = 0; mi < 2; mi++) {
                const int row = wr * 32 + mi * 16 + g;
                a[mi][0] = Aw[row * 20 + kw + tc];
                a[mi][1] = Aw[(row + 8) * 20 + kw + tc];
                a[mi][2] = Aw[row * 20 + kw + tc + 4];
                a[mi][3] = Aw[(row + 8) * 20 + kw + tc + 4];
            }
#pragma unroll
            for (int ni = 0; ni < 8; ni++) {
                const int br = wn * 64 + ni * 8 + g;
                const uint32_t b0 = Bw[br * 20 + kw + tc];
                const uint32_t b1 = Bw[br * 20 + kw + tc + 4];
                MMA_BF16(cacc[0][ni], a[0], b0, b1);
                MMA_BF16(cacc[1][ni], a[1], b0, b1);
            }
        }
    }

#pragma unroll
    for (int mi = 0; mi < 2; mi++) {
        const int row = m0 + wr * 32 + mi * 16 + g;
#pragma unroll
        for (int ni = 0; ni < 8; ni++) {
            const int col = n0 + wn * 64 + ni * 8 + tc * 2;
            if (mode == 2) {
                const float2 x0 = *(const float2*)(resid + (size_t)row * NDIM + col);
                const float2 x1 = *(const float2*)(resid + (size_t)(row + 8) * NDIM + col);
                *(float2*)(Cf + (size_t)row * NDIM + col) =
                    make_float2(cacc[mi][ni][0] + x0.x, cacc[mi][ni][1] + x0.y);
                *(float2*)(Cf + (size_t)(row + 8) * NDIM + col) =
                    make_float2(cacc[mi][ni][2] + x1.x, cacc[mi][ni][3] + x1.y);
            } else if (mode == 3) {
                *(uint32_t*)(Ch + (size_t)row * NDIM + col) =
                    packh(cacc[mi][ni][0], cacc[mi][ni][1]);
                *(uint32_t*)(Ch + (size_t)(row + 8) * NDIM + col) =
                    packh(cacc[mi][ni][2], cacc[mi][ni][3]);
            } else {
                *(uint32_t*)(Cb + (size_t)row * NDIM + col) =
                    packbf(cacc[mi][ni][0] * scale, cacc[mi][ni][1] * scale);
                *(uint32_t*)(Cb + (size_t)(row + 8) * NDIM + col) =
                    packbf(cacc[mi][ni][2] * scale, cacc[mi][ni][3] * scale);
            }
        }
    }
}

__global__ void __launch_bounds__(256) qkv_bgemm_kernel()
{
    const int z = blockIdx.z;
    if (z == 2) {
        bgemm_body(g_xb, g_Wvb, nullptr, g_V, nullptr, nullptr, 3, 1.0f);
    } else {
        const __nv_bfloat16* B = (z == 0) ? g_Wqb : g_Wkb;
        __nv_bfloat16* C       = (z == 0) ? g_Q   : g_K;
        const float scale = (z == 0) ? 0.18033688f : 1.0f;   // 0.125*log2(e)
        bgemm_body(g_xb, B, C, nullptr, nullptr, nullptr, 0, scale);
    }
}

__global__ void __launch_bounds__(256) oproj_bgemm_kernel(const float* __restrict__ x,
                                                          float* __restrict__ out)
{
    bgemm_body(g_AO, g_Wob, nullptr, nullptr, out, x, 2, 1.0f);
}

// ---------------------------------------------------------------------------
// flash attention, OCCUPANCY-2: CTA = 64 q x 128 kv, 8 warps (4 q-blocks of
// 16 rows x 2 kv-halves), __launch_bounds__(256,2) -> 2 CTAs/SM = 4 warps/SMSP.
// S = QK^T bf16 mma; P = ex2.f16x2; PV fp16 mma; row sums via ones-column
// on the tensor pipe. Pipe-interleaved tile body (R13 schedule).
// ---------------------------------------------------------------------------
#define A_SW   36
#define A_ROWB 144
#define OQ  0                 // 64 x 144B = 9216
#define OK0 9216
#define OK1 27648
#define OV0 46080
#define OV1 64512
#define OLS 82944             // 128 floats
#define ATT_SMEM (OLS + 768)

static __device__ __forceinline__ void ld_tileK(uint32_t dst, const void* src_,
                                                int row0, int tid)
{
    const __nv_bfloat16* src = (const __nv_bfloat16*)src_;
#pragma unroll
    for (int i = 0; i < 4; i++) {
        const int idx = tid + i * 256;
        const int r = idx >> 3, c = idx & 7;
        cpa16(dst + r * A_ROWB + c * 16, src + (size_t)(row0 + r) * NDIM + c * 8);
    }
}
static __device__ __forceinline__ void ld_tileQ(uint32_t dst,
                                                const __nv_bfloat16* src,
                                                int row0, int tid)
{
#pragma unroll
    for (int i = 0; i < 2; i++) {
        const int idx = tid + i * 256;
        const int r = idx >> 3, c = idx & 7;
        cpa16(dst + r * A_ROWB + c * 16, src + (size_t)(row0 + r) * NDIM + c * 8);
    }
}

// S-mma for one ni chunk: 2 ldsm + 4 mma (bf16, single 16-row block)
#define SMMA(ni)                                                             \
{                                                                            \
    uint32_t kf[8];                                                          \
    const uint32_t a0 = kaddr + (uint32_t)((ni) * 8) * A_ROWB;               \
    LDSM_X4(kf[0], kf[1], kf[2], kf[3], a0);                                 \
    LDSM_X4(kf[4], kf[5], kf[6], kf[7], a0 + 64);                            \
    _Pragma("unroll")                                                        \
    for (int k4 = 0; k4 < 4; k4++)                                           \
        MMA_BF16(sacc[ni], qfr[k4], kf[k4 * 2], kf[k4 * 2 + 1]);             \
}

// exp2 in f16x2 for one ni chunk: 2 cvt + 2 MUFU -> P fp16 frags
#define EXPP(ni)                                                             \
{                                                                            \
    pfr[ni][0] = ex2h2(packh(sacc[ni][0], sacc[ni][1]));                     \
    pfr[ni][1] = ex2h2(packh(sacc[ni][2], sacc[ni][3]));                     \
}

// PV ldsm block for one ki: V data (nd 0..7) + ones column (nd 8)
#define PVLD(ki)                                                             \
    _Pragma("unroll")                                                        \
    for (int db = 0; db < 4; db++) {                                         \
        const uint32_t addr = vbase +                                        \
            (uint32_t)(wc * 64 + (ki) * 16 + (mat & 1) * 8 + lr) * A_ROWB +  \
            (uint32_t)(db * 16 + (mat >> 1) * 8) * 2;                        \
        LDSM_X4_T(bfr[db * 2][0], bfr[db * 2][1],                            \
                  bfr[db * 2 + 1][0], bfr[db * 2 + 1][1], addr);             \
    }                                                                        \
    {                                                                        \
        uint32_t dum0, dum1;                                                 \
        const uint32_t addr = vbase +                                        \
            (uint32_t)(wc * 64 + (ki) * 16 + (mat & 1) * 8 + lr) * A_ROWB +  \
            (uint32_t)(64 + (mat >> 1) * 8) * 2;                             \
        LDSM_X4_T(bfr[8][0], bfr[8][1], dum0, dum1, addr);                   \
        (void)dum0; (void)dum1;                                              \
    }

// PV mma block for one ki (fp16), incl. ones block nd=8 (row sums)
#define PVMMA(ki)                                                            \
{                                                                            \
    uint32_t a[4] = { pfr[2 * (ki)][0],     pfr[2 * (ki)][1],                \
                      pfr[2 * (ki) + 1][0], pfr[2 * (ki) + 1][1] };          \
    _Pragma("unroll")                                                        \
    for (int nd = 0; nd < 9; nd++)                                           \
        MMA_F16(oacc[nd], a, bfr[nd][0], bfr[nd][1]);                        \
}

__global__ void __launch_bounds__(256, 2) attn_kernel()
{
    extern __shared__ char smc[];
    const uint32_t smb = s2u(smc);

    const int tid  = threadIdx.x;
    const int wid  = tid >> 5;
    const int lane = tid & 31;
    const int wr = wid & 3;          // q block (16 rows)
    const int wc = wid >> 2;         // kv-half (64 cols)
    const int g  = lane >> 2;
    const int tc = lane & 3;
    const int row = wr * 16 + g;

    const int q0 = blockIdx.x * 64;
    const int bh = blockIdx.y;
    const int b  = bh >> 3;
    const int h  = bh & 7;

    const __nv_bfloat16* Qg = g_Q + (size_t)b * SEQ * NDIM + h * DH;
    const __nv_bfloat16* Kg = g_K + (size_t)b * SEQ * NDIM + h * DH;
    const __half*        Vg = g_V + (size_t)b * SEQ * NDIM + h * DH;

    float* ls = (float*)(smc + OLS);

    ld_tileQ(smb + OQ,  Qg, q0, tid);
    ld_tileK(smb + OK0, Kg, 0,  tid);
    ld_tileK(smb + OV0, Vg, 0,  tid);
    cpa_commit();

    // init ones-column pads of BOTH V buffers (col 64 = 1.0h, rest 0)
    {
        const int buf = tid >> 7, r = tid & 127;
        uint32_t off = (buf ? OV1 : OV0) + (uint32_t)r * A_ROWB + 128;
        *(uint4*)(smc + off) = make_uint4(0x00003C00u, 0u, 0u, 0u);
    }

    cpa_wait0();
    __syncthreads();

    // hoist Q fragments (4 k16-steps x 4 regs)
    uint32_t qfr[4][4];
    {
        const uint32_t* Qw = (const uint32_t*)smc;
#pragma unroll
        for (int k4 = 0; k4 < 4; k4++) {
            qfr[k4][0] = Qw[row * A_SW + k4 * 8 + tc];
            qfr[k4][1] = Qw[(row + 8) * A_SW + k4 * 8 + tc];
            qfr[k4][2] = Qw[row * A_SW + k4 * 8 + tc + 4];
            qfr[k4][3] = Qw[(row + 8) * A_SW + k4 * 8 + tc + 4];
        }
    }

    float oacc[9][4];
#pragma unroll
    for (int nd = 0; nd < 9; nd++)
#pragma unroll
        for (int c = 0; c < 4; c++) oacc[nd][c] = 0.f;

    const int mat = lane >> 3, lr = lane & 7;
    const uint32_t klane_off =
        (uint32_t)(wc * 64 + lr) * A_ROWB + (uint32_t)((lane >> 4) * 32 + mat % 2 * 16);

    for (int j = 0; j < NT; j++) {
        if (j + 1 < NT) {
            const int nb = (j + 1) & 1;
            ld_tileK(smb + (nb ? OK1 : OK0), Kg, (j + 1) * 128, tid);
            ld_tileK(smb + (nb ? OV1 : OV0), Vg, (j + 1) * 128, tid);
            cpa_commit();
        }

        const uint32_t kaddr = smb + ((j & 1) ? OK1 : OK0) + klane_off;
        const uint32_t vbase = smb + ((j & 1) ? OV1 : OV0);

        float sacc[8][4];
#pragma unroll
        for (int ni = 0; ni < 8; ni++)
#pragma unroll
            for (int c = 0; c < 4; c++) sacc[ni][c] = 0.f;

        uint32_t pfr[8][2];

        // ---- interleaved S-mma / exp ----
        SMMA(0) SMMA(1)
        SMMA(2) EXPP(0)
        SMMA(3) EXPP(1)
        SMMA(4) EXPP(2)
        SMMA(5) EXPP(3)
        SMMA(6) EXPP(4)
        SMMA(7) EXPP(5)

        // ---- PV (fp16) with trailing exps woven in ----
        {
            uint32_t bfr[9][2];
            PVLD(0) EXPP(6) PVMMA(0)
            PVLD(1) EXPP(7) PVMMA(1)
            PVLD(2) PVMMA(2)
            PVLD(3) PVMMA(3)
        }

        if (j + 1 < NT) {
            cpa_wait0();
            __syncthreads();
        }
    }

    // row sums (tensor-computed, col 64 = ones) -> ls
    if (tc == 0) {
        ls[wc * 64 + row]     = oacc[8][0];
        ls[wc * 64 + row + 8] = oacc[8][2];
    }

    // ---- epilogue: combine kv-halves in smem, normalize, store bf16 ----
    __syncthreads();
    float* Osm = (float*)(smc + OK0);   // 64 x 64, stride 68 floats (17408B)
    if (wc == 0) {
#pragma unroll
        for (int nd = 0; nd < 8; nd++) {
            const int col = nd * 8 + tc * 2;
            Osm[row * 68 + col]           = oacc[nd][0];
            Osm[row * 68 + col + 1]       = oacc[nd][1];
            Osm[(row + 8) * 68 + col]     = oacc[nd][2];
            Osm[(row + 8) * 68 + col + 1] = oacc[nd][3];
        }
    }
    __syncthreads();
    if (wc == 1) {
#pragma unroll
        for (int nd = 0; nd < 8; nd++) {
            const int col = nd * 8 + tc * 2;
            Osm[row * 68 + col]           += oacc[nd][0];
            Osm[row * 68 + col + 1]       += oacc[nd][1];
            Osm[(row + 8) * 68 + col]     += oacc[nd][2];
            Osm[(row + 8) * 68 + col + 1] += oacc[nd][3];
        }
    }
    __syncthreads();

    const int orow = tid >> 2;
    const int c0   = (tid & 3) * 16;
    const float inv = 1.f / (ls[orow] + ls[64 + orow]);
    __nv_bfloat16* Og = g_AO + (size_t)b * SEQ * NDIM +
                        (size_t)(q0 + orow) * NDIM + h * DH + c0;
#pragma unroll
    for (int c = 0; c < 16; c += 2)
        *(uint32_t*)(Og + c) = packbf(Osm[orow * 68 + c0 + c] * inv,
                                      Osm[orow * 68 + c0 + c + 1] * inv);
}

// ---------------------------------------------------------------------------
extern "C" void kernel_launch(void* const* d_in, const int* in_sizes, int n_in,
                              void* d_out, int out_size)
{
    const float* x  = (const float*)d_in[0];
    const float* Wq = (const float*)d_in[1];
    const float* Wk = (const float*)d_in[2];
    const float* Wv = (const float*)d_in[3];
    const float* Wo = (const float*)d_in[4];
    float* out = (float*)d_out;

    __nv_bfloat16* dxb;
    cudaGetSymbolAddress((void**)&dxb, g_xb);

    cudaFuncSetAttribute(attn_kernel,
                         cudaFuncAttributeMaxDynamicSharedMemorySize, ATT_SMEM);

    cvt_kernel<<<(MTOT * NDIM) / 1024, 256>>>(x, dxb);
    dim3 gw((NDIM * NDIM) / 1024, 1, 4);
    cvtw_kernel<<<gw, 256>>>(Wq, Wk, Wv, Wo);

    dim3 gqkv(NDIM / 128, MTOT / 128, 3);
    qkv_bgemm_kernel<<<gqkv, 256>>>();

    dim3 gattn(SEQ / 64, 16);
    attn_kernel<<<gattn, 256, ATT_SMEM>>>();

    dim3 go(NDIM / 128, MTOT / 128);
    oproj_bgemm_kernel<<<go, 256>>>(x, out);
}